// round 14
// baseline (speedup 1.0000x reference)
#include <cuda_runtime.h>
#include <cuda_fp16.h>
#include <stdint.h>
#include <math.h>

#define BATCH 64
#define CDIM  256
#define NPOS  1024
#define SLOTS 8
#define DDIM  256
#define NITER 3
#define LN_EPS 1e-5f
#define ATT_SCALE 0.0625f   // D^-0.5
#define NCHUNK 32           // attention n-chunks (32 rows each)
#define KPAD  (DDIM + 8)    // fp16 smem row padding: 528B rows (16B-aligned)
#define QPAD  (DDIM + 4)    // fp32 smem row padding: 1040B rows (16B-aligned)

// ---------------- device scratch ----------------
__device__ __half g_xh[BATCH * NPOS * CDIM];         // fp16 LN(x)
__device__ __half g_wcat[512 * CDIM];                // [n][c] fp16 (wk rows then wv rows)
__device__ __half g_kh[BATCH * NPOS * DDIM];         // fp16 k
__device__ __half g_vh[BATCH * NPOS * DDIM];         // fp16 v
__device__ float g_slots[BATCH * SLOTS * DDIM];
__device__ float g_q    [BATCH * SLOTS * DDIM];
__device__ __half g_upd [NCHUNK * BATCH * SLOTS * DDIM];  // fp16 partials
// fp16 transposed weights [c][d]
__device__ __half g_wqTh [CDIM * DDIM];
__device__ __half g_w1Th [DDIM * DDIM];
__device__ __half g_w2Th [DDIM * DDIM];
__device__ __half g_wihTh[DDIM * 3 * DDIM];
__device__ __half g_whhTh[DDIM * 3 * DDIM];

// ---------------- helpers ----------------
__device__ __forceinline__ void cp16(void* s, const void* g) {
    unsigned sa = (unsigned)__cvta_generic_to_shared(s);
    asm volatile("cp.async.cg.shared.global [%0], [%1], 16;\n" :: "r"(sa), "l"(g));
}
__device__ __forceinline__ void cp_commit() { asm volatile("cp.async.commit_group;\n"); }
template<int N> __device__ __forceinline__ void cp_wait() {
    asm volatile("cp.async.wait_group %0;\n" :: "n"(N));
}
__device__ __forceinline__ uint4 ldm4(const void* p) {
    uint4 r;
    unsigned a = (unsigned)__cvta_generic_to_shared(p);
    asm volatile("ldmatrix.sync.aligned.m8n8.x4.shared.b16 {%0,%1,%2,%3}, [%4];"
                 : "=r"(r.x), "=r"(r.y), "=r"(r.z), "=r"(r.w) : "r"(a));
    return r;
}

// ---------------- one-time prep ----------------
__global__ void k_prep(const float* __restrict__ mu,
                       const float* __restrict__ wk, const float* __restrict__ wv,
                       const float* __restrict__ wq, const float* __restrict__ wih,
                       const float* __restrict__ whh, const float* __restrict__ w1,
                       const float* __restrict__ w2) {
    int i = blockIdx.x * 256 + threadIdx.x;
    if (i < 131072) {
        g_slots[i] = mu[i & (SLOTS * DDIM - 1)];
        float w = (i < 65536) ? wk[i] : wv[i - 65536];
        g_wcat[i] = __float2half(w);
    }
    if (i < 65536) {
        int d = i >> 8, c = i & 255;
        g_wqTh[c * 256 + d] = __float2half(wq[i]);
    } else if (i < 131072) {
        int j = i - 65536; int d = j >> 8; int c = j & 255;
        g_w1Th[c * 256 + d] = __float2half(w1[j]);
    } else if (i < 196608) {
        int j = i - 131072; int d = j >> 8; int c = j & 255;
        g_w2Th[c * 256 + d] = __float2half(w2[j]);
    } else if (i < 393216) {
        int j = i - 196608; int g = j >> 8; int c = j & 255;
        g_wihTh[c * 768 + g] = __float2half(wih[j]);
    } else if (i < 589824) {
        int j = i - 393216; int g = j >> 8; int c = j & 255;
        g_whhTh[c * 768 + g] = __float2half(whh[j]);
    }
}

// ---------------- transpose + input LayerNorm -> fp16 (+ fused iter-0 qproj) ----------------
__global__ void k_ln_in(const float* __restrict__ x,
                        const float* __restrict__ gam,
                        const float* __restrict__ bet,
                        const float* __restrict__ slg,
                        const float* __restrict__ slb) {
    __shared__ float tile[CDIM][33];
    __shared__ float mu_s[32], rs_s[32];
    int b  = blockIdx.y;
    int n0 = blockIdx.x * 32;
    int tid = threadIdx.x;
    const float* xb = x + (size_t)b * CDIM * NPOS;

    for (int i = tid; i < CDIM * 32; i += 256) {
        int c = i >> 5, n = i & 31;
        tile[c][n] = xb[c * NPOS + n0 + n];
    }
    __syncthreads();

    int warp = tid >> 5, lane = tid & 31;
    for (int col = warp; col < 32; col += 8) {
        float s = 0.f, s2 = 0.f;
        #pragma unroll
        for (int c = lane; c < CDIM; c += 32) {
            float v = tile[c][col];
            s += v; s2 += v * v;
        }
        #pragma unroll
        for (int o = 16; o; o >>= 1) {
            s  += __shfl_xor_sync(0xffffffffu, s,  o);
            s2 += __shfl_xor_sync(0xffffffffu, s2, o);
        }
        if (lane == 0) {
            float m   = s * (1.f / CDIM);
            float var = s2 * (1.f / CDIM) - m * m;
            mu_s[col] = m;
            rs_s[col] = rsqrtf(var + LN_EPS);
        }
    }
    __syncthreads();

    float gg = gam[tid], bb = bet[tid];
    size_t base = ((size_t)b * NPOS + n0) * CDIM + tid;
    #pragma unroll 8
    for (int n = 0; n < 32; n++) {
        float v = (tile[tid][n] - mu_s[n]) * rs_s[n] * gg + bb;
        g_xh[base + (size_t)n * CDIM] = __float2half(v);
    }

    // fused iter-0 q projection (4 early blocks): q = LN_s(slots_mu) @ wq^T into g_q[batch 0]
    if (blockIdx.x != 0 || blockIdx.y >= 4) return;
    int dq = blockIdx.y;
    __syncthreads();
    float* bufa = &tile[0][0];
    float (*sn)[DDIM] = (float(*)[DDIM])bufa;
    float (*part)[SLOTS][64] = (float(*)[SLOTS][64])(bufa + 2048);

    {
        int s = warp;
        const float* row = g_slots + (size_t)s * DDIM;
        float v[8]; float sum = 0.f, sq = 0.f;
        #pragma unroll
        for (int j = 0; j < 8; j++) {
            v[j] = row[lane + 32 * j];
            sum += v[j]; sq += v[j] * v[j];
        }
        #pragma unroll
        for (int o = 16; o; o >>= 1) {
            sum += __shfl_xor_sync(0xffffffffu, sum, o);
            sq  += __shfl_xor_sync(0xffffffffu, sq,  o);
        }
        float m = sum * (1.f / DDIM);
        float r = rsqrtf(sq * (1.f / DDIM) - m * m + LN_EPS);
        #pragma unroll
        for (int j = 0; j < 8; j++) {
            int c = lane + 32 * j;
            sn[s][c] = (v[j] - m) * r * slg[c] + slb[c];
        }
    }
    __syncthreads();

    int dd = tid & 63, pp = tid >> 6;
    int d  = dq * 64 + dd;
    float acc[SLOTS];
    #pragma unroll
    for (int s = 0; s < SLOTS; s++) acc[s] = 0.f;
    #pragma unroll 8
    for (int cc = 0; cc < 64; cc++) {
        int c = pp * 64 + cc;
        float ww = __half2float(g_wqTh[c * DDIM + d]);
        #pragma unroll
        for (int s = 0; s < SLOTS; s++) acc[s] = fmaf(sn[s][c], ww, acc[s]);
    }
    #pragma unroll
    for (int s = 0; s < SLOTS; s++) part[pp][s][dd] = acc[s];
    __syncthreads();

    for (int o = tid; o < SLOTS * 64; o += 256) {
        int s = o >> 6, dd2 = o & 63;
        float v = part[0][s][dd2] + part[1][s][dd2] + part[2][s][dd2] + part[3][s][dd2];
        g_q[(size_t)s * DDIM + dq * 64 + dd2] = v;
    }
}

// ---------------- big GEMM: fp16, K=256, 3-stage cp.async + ldmatrix + mma ----------------
__global__ void __launch_bounds__(256, 2) k_gemm_kv_mma() {
    __shared__ __half As[3][128][40];
    __shared__ __half Bs[3][128][40];
    int n0 = blockIdx.x * 128;
    int m0 = blockIdx.y * 128;
    int tid = threadIdx.x, lane = tid & 31, warp = tid >> 5;
    int wm = (warp & 3) * 32, wn = (warp >> 2) * 64;
    __half* Out = (n0 < 256) ? g_kh : g_vh;
    int ncol0 = n0 & 255;
    int lr = tid >> 1, lc = (tid & 1) * 8;

    int g8 = lane >> 3, l8 = lane & 7;
    int aro = l8 + (g8 & 1) * 8, aco = (g8 >> 1) * 8;
    int bro = l8 + (g8 >> 1) * 8, bco = (g8 & 1) * 8;

    float acc[2][8][4];
    #pragma unroll
    for (int i = 0; i < 2; i++)
        #pragma unroll
        for (int j = 0; j < 8; j++)
            #pragma unroll
            for (int q = 0; q < 4; q++) acc[i][j][q] = 0.f;

    auto issue = [&](int kti, int buf) {
        int kt = kti * 32;
        const __half* ga = g_xh + (size_t)(m0 + lr) * CDIM + kt + lc;
        const __half* gb = g_wcat + (size_t)(n0 + lr) * CDIM + kt + lc;
        cp16(&As[buf][lr][lc],      ga);
        cp16(&As[buf][lr][lc + 16], ga + 16);
        cp16(&Bs[buf][lr][lc],      gb);
        cp16(&Bs[buf][lr][lc + 16], gb + 16);
    };

    issue(0, 0); cp_commit();
    issue(1, 1); cp_commit();

    for (int i = 0; i < 8; i++) {
        if (i < 7) cp_wait<1>(); else cp_wait<0>();
        __syncthreads();
        if (i < 6) { issue(i + 2, (i + 2) % 3); cp_commit(); }
        int buf = i % 3;

        #pragma unroll
        for (int k16 = 0; k16 < 32; k16 += 16) {
            uint4 av[2], bv[4];
            #pragma unroll
            for (int im = 0; im < 2; im++)
                av[im] = ldm4(&As[buf][wm + im * 16 + aro][k16 + aco]);
            #pragma unroll
            for (int t = 0; t < 4; t++)
                bv[t] = ldm4(&Bs[buf][wn + t * 16 + bro][k16 + bco]);

            #pragma unroll
            for (int im = 0; im < 2; im++)
                #pragma unroll
                for (int t = 0; t < 4; t++) {
                    asm volatile(
                        "mma.sync.aligned.m16n8k16.row.col.f32.f16.f16.f32 "
                        "{%0,%1,%2,%3}, {%4,%5,%6,%7}, {%8,%9}, {%0,%1,%2,%3};\n"
                        : "+f"(acc[im][2*t][0]), "+f"(acc[im][2*t][1]),
                          "+f"(acc[im][2*t][2]), "+f"(acc[im][2*t][3])
                        : "r"(av[im].x), "r"(av[im].y), "r"(av[im].z), "r"(av[im].w),
                          "r"(bv[t].x), "r"(bv[t].y));
                    asm volatile(
                        "mma.sync.aligned.m16n8k16.row.col.f32.f16.f16.f32 "
                        "{%0,%1,%2,%3}, {%4,%5,%6,%7}, {%8,%9}, {%0,%1,%2,%3};\n"
                        : "+f"(acc[im][2*t+1][0]), "+f"(acc[im][2*t+1][1]),
                          "+f"(acc[im][2*t+1][2]), "+f"(acc[im][2*t+1][3])
                        : "r"(av[im].x), "r"(av[im].y), "r"(av[im].z), "r"(av[im].w),
                          "r"(bv[t].z), "r"(bv[t].w));
                }
        }
        __syncthreads();
    }

    #pragma unroll
    for (int im = 0; im < 2; im++)
        #pragma unroll
        for (int jn = 0; jn < 8; jn++) {
            int row = m0 + wm + im * 16 + (lane >> 2);
            int col = ncol0 + wn + jn * 8 + (lane & 3) * 2;
            __half* p = Out + (size_t)row * DDIM + col;
            *(__half2*)p = __floats2half2_rn(acc[im][jn][0], acc[im][jn][1]);
            *(__half2*)(p + 8 * DDIM) = __floats2half2_rn(acc[im][jn][2], acc[im][jn][3]);
        }
}

// ---------------- attention: smem-tiled, vectorized logits + partial updates ----------------
__global__ void __launch_bounds__(256) k_attn(float* __restrict__ attn_out, int q_bcast) {
    int b = blockIdx.x, ch = blockIdx.y;
    int n0 = ch * 32;
    __shared__ __half ksm[32][KPAD];     // 528B rows, 16B-aligned
    __shared__ __half vsm[32][KPAD];
    __shared__ float  qs[SLOTS][QPAD];   // 1040B rows, 16B-aligned
    __shared__ float  as_[32][SLOTS];
    int tid = threadIdx.x;

    {   // load q
        int qb = q_bcast ? 0 : b;
        const float* qsrc = g_q + (size_t)qb * SLOTS * DDIM;
        #pragma unroll
        for (int i = 0; i < 8; i++) {
            int idx = tid + i * 256;
            qs[idx >> 8][idx & 255] = qsrc[idx];
        }
    }
    {   // load k,v tiles via uint4
        const __half* kg = g_kh + (size_t)(b * NPOS + n0) * DDIM;
        const __half* vg = g_vh + (size_t)(b * NPOS + n0) * DDIM;
        #pragma unroll
        for (int i = 0; i < 4; i++) {
            int idx = tid + i * 256;
            int row = idx >> 5, seg = idx & 31;
            *(uint4*)&ksm[row][seg * 8] = *(const uint4*)(kg + (size_t)row * DDIM + seg * 8);
            *(uint4*)&vsm[row][seg * 8] = *(const uint4*)(vg + (size_t)row * DDIM + seg * 8);
        }
    }
    __syncthreads();

    // logits: thread-per-(row,slot), float4 smem reads (LDS.128, conflict-free)
    {
        int r = tid >> 3, s = tid & 7;
        const float4* krow = (const float4*)&ksm[r][0];
        const float4* qrow = (const float4*)&qs[s][0];
        float acc = 0.f;
        #pragma unroll 8
        for (int i = 0; i < 32; i++) {
            float4 kq = krow[i];
            __half2* kh = (__half2*)&kq;
            float4 q0 = qrow[i * 2], q1 = qrow[i * 2 + 1];
            float2 k0 = __half22float2(kh[0]), k1 = __half22float2(kh[1]);
            float2 k2 = __half22float2(kh[2]), k3 = __half22float2(kh[3]);
            acc += k0.x*q0.x + k0.y*q0.y + k1.x*q0.z + k1.y*q0.w
                 + k2.x*q1.x + k2.y*q1.y + k3.x*q1.z + k3.y*q1.w;
        }
        float logit = acc * ATT_SCALE;
        float mx = logit;
        #pragma unroll
        for (int m = 1; m < 8; m <<= 1)
            mx = fmaxf(mx, __shfl_xor_sync(0xffffffffu, mx, m));
        float e = expf(logit - mx);
        float ssum = e;
        #pragma unroll
        for (int m = 1; m < 8; m <<= 1)
            ssum += __shfl_xor_sync(0xffffffffu, ssum, m);
        float a = e / ssum;
        as_[r][s] = a;
        if (attn_out)
            attn_out[(size_t)(b * NPOS + n0 + r) * SLOTS + s] = a;
    }
    __syncthreads();

    // partial updates: thread owns channel c, v from smem
    int c = tid;
    float acc[SLOTS];
    #pragma unroll
    for (int s = 0; s < SLOTS; s++) acc[s] = 0.f;
    #pragma unroll 8
    for (int nn = 0; nn < 32; nn++) {
        float vv = __half2float(vsm[nn][c]);
        #pragma unroll
        for (int s = 0; s < SLOTS; s++) acc[s] = fmaf(as_[nn][s], vv, acc[s]);
    }
    __half* up = g_upd + (size_t)((ch * BATCH + b) * SLOTS) * DDIM + c;
    #pragma unroll
    for (int s = 0; s < SLOTS; s++) up[(size_t)s * DDIM] = __float2half(acc[s]);
}

// ---------------- slot update: grid (64,4), 2 slots/block, 512 threads, split-c ----------------
__global__ void __launch_bounds__(512) k_slot_update(
        const float* __restrict__ bih, const float* __restrict__ bhh,
        const float* __restrict__ lg,  const float* __restrict__ lb,
        const float* __restrict__ b1,  const float* __restrict__ b2,
        const float* __restrict__ slg, const float* __restrict__ slb,
        float* __restrict__ out_slots, int write_out, int write_q) {
    int b = blockIdx.x, sq = blockIdx.y;     // sq: slot-pair 0..3
    __shared__ float u [2][DDIM];
    __shared__ float h [2][DDIM];
    __shared__ float nh[2][DDIM];
    __shared__ float hm[2][DDIM];
    __shared__ float pr[12][DDIM];
    int tid = threadIdx.x;
    int d = tid & 255, cpart = tid >> 8;
    int c0 = cpart * 128;
    int sbase = sq * 2;

    for (int i = tid; i < 2 * DDIM; i += 512) {
        int s = i >> 8, c = i & 255;
        float a = 0.f;
        #pragma unroll
        for (int chn = 0; chn < NCHUNK; chn++)
            a += __half2float(g_upd[(size_t)((chn * BATCH + b) * SLOTS + sbase + s) * DDIM + c]);
        u[s][c] = a;
        h[s][c] = g_slots[(size_t)(b * SLOTS + sbase + s) * DDIM + c];
    }
    __syncthreads();

    float ir[2] = {0,0}, iz[2] = {0,0}, in_[2] = {0,0};
    float hr[2] = {0,0}, hz[2] = {0,0}, hn_[2] = {0,0};
    #pragma unroll 4
    for (int cc = 0; cc < 128; cc++) {
        int c = c0 + cc;
        float a0 = __half2float(g_wihTh[c * 768 + d]);
        float a1 = __half2float(g_wihTh[c * 768 + 256 + d]);
        float a2 = __half2float(g_wihTh[c * 768 + 512 + d]);
        float c0w = __half2float(g_whhTh[c * 768 + d]);
        float c1w = __half2float(g_whhTh[c * 768 + 256 + d]);
        float c2w = __half2float(g_whhTh[c * 768 + 512 + d]);
        #pragma unroll
        for (int s = 0; s < 2; s++) {
            float uu = u[s][c], hh = h[s][c];
            ir[s] = fmaf(a0, uu, ir[s]); iz[s] = fmaf(a1, uu, iz[s]); in_[s] = fmaf(a2, uu, in_[s]);
            hr[s] = fmaf(c0w, hh, hr[s]); hz[s] = fmaf(c1w, hh, hz[s]); hn_[s] = fmaf(c2w, hh, hn_[s]);
        }
    }
    if (cpart == 1) {
        #pragma unroll
        for (int s = 0; s < 2; s++) {
            pr[s][d]      = ir[s];  pr[2 + s][d]  = iz[s];  pr[4 + s][d]  = in_[s];
            pr[6 + s][d]  = hr[s];  pr[8 + s][d]  = hz[s];  pr[10 + s][d] = hn_[s];
        }
    }
    __syncthreads();
    if (cpart == 0) {
        float bir = bih[d], biz = bih[DDIM + d], bin = bih[2 * DDIM + d];
        float bhr = bhh[d], bhz = bhh[DDIM + d], bhn = bhh[2 * DDIM + d];
        #pragma unroll
        for (int s = 0; s < 2; s++) {
            float rI = ir[s] + pr[s][d],     zI = iz[s] + pr[2 + s][d], nI = in_[s] + pr[4 + s][d];
            float rH = hr[s] + pr[6 + s][d], zH = hz[s] + pr[8 + s][d], nH = hn_[s] + pr[10 + s][d];
            float r = 1.f / (1.f + expf(-(rI + bir + rH + bhr)));
            float z = 1.f / (1.f + expf(-(zI + biz + zH + bhz)));
            float n = tanhf(nI + bin + r * (nH + bhn));
            nh[s][d] = (1.f - z) * n + z * h[s][d];
        }
    }
    __syncthreads();

    int warp = tid >> 5, lane = tid & 31;
    if (warp < 2) {
        int s = warp;
        float v[8]; float sum = 0.f, sq2 = 0.f;
        #pragma unroll
        for (int j = 0; j < 8; j++) {
            v[j] = nh[s][lane + 32 * j];
            sum += v[j]; sq2 += v[j] * v[j];
        }
        #pragma unroll
        for (int o = 16; o; o >>= 1) {
            sum += __shfl_xor_sync(0xffffffffu, sum, o);
            sq2 += __shfl_xor_sync(0xffffffffu, sq2, o);
        }
        float m = sum * (1.f / DDIM);
        float rs = rsqrtf(sq2 * (1.f / DDIM) - m * m + LN_EPS);
        #pragma unroll
        for (int j = 0; j < 8; j++) {
            int c = lane + 32 * j;
            u[s][c] = (v[j] - m) * rs * lg[c] + lb[c];
        }
    }
    __syncthreads();

    float m2[2] = {0,0};
    #pragma unroll 4
    for (int cc = 0; cc < 128; cc++) {
        int c = c0 + cc;
        float ww = __half2float(g_w1Th[c * DDIM + d]);
        #pragma unroll
        for (int s = 0; s < 2; s++) m2[s] = fmaf(u[s][c], ww, m2[s]);
    }
    if (cpart == 1) {
        #pragma unroll
        for (int s = 0; s < 2; s++) pr[s][d] = m2[s];
    }
    __syncthreads();
    if (cpart == 0) {
        float bb1 = b1[d];
        #pragma unroll
        for (int s = 0; s < 2; s++) hm[s][d] = fmaxf(m2[s] + pr[s][d] + bb1, 0.f);
    }
    __syncthreads();

    float o2[2] = {0,0};
    #pragma unroll 4
    for (int cc = 0; cc < 128; cc++) {
        int c = c0 + cc;
        float ww = __half2float(g_w2Th[c * DDIM + d]);
        #pragma unroll
        for (int s = 0; s < 2; s++) o2[s] = fmaf(hm[s][c], ww, o2[s]);
    }
    if (cpart == 1) {
        #pragma unroll
        for (int s = 0; s < 2; s++) pr[2 + s][d] = o2[s];
    }
    __syncthreads();
    if (cpart == 0) {
        float bb2 = b2[d];
        #pragma unroll
        for (int s = 0; s < 2; s++) {
            float res = nh[s][d] + o2[s] + pr[2 + s][d] + bb2;
            h[s][d] = res;
            g_slots[(size_t)(b * SLOTS + sbase + s) * DDIM + d] = res;
            if (write_out && out_slots)
                out_slots[(size_t)(b * SLOTS + sbase + s) * DDIM + d] = res;
        }
    }
    __syncthreads();

    if (!write_q) return;

    if (warp < 2) {
        int s = warp;
        float v[8]; float sum = 0.f, sq2 = 0.f;
        #pragma unroll
        for (int j = 0; j < 8; j++) {
            v[j] = h[s][lane + 32 * j];
            sum += v[j]; sq2 += v[j] * v[j];
        }
        #pragma unroll
        for (int o = 16; o; o >>= 1) {
            sum += __shfl_xor_sync(0xffffffffu, sum, o);
            sq2 += __shfl_xor_sync(0xffffffffu, sq2, o);
        }
        float m = sum * (1.f / DDIM);
        float rs = rsqrtf(sq2 * (1.f / DDIM) - m * m + LN_EPS);
        #pragma unroll
        for (int j = 0; j < 8; j++) {
            int c = lane + 32 * j;
            u[s][c] = (v[j] - m) * rs * slg[c] + slb[c];
        }
    }
    __syncthreads();
    float q2[2] = {0,0};
    #pragma unroll 4
    for (int cc = 0; cc < 128; cc++) {
        int c = c0 + cc;
        float ww = __half2float(g_wqTh[c * DDIM + d]);
        #pragma unroll
        for (int s = 0; s < 2; s++) q2[s] = fmaf(u[s][c], ww, q2[s]);
    }
    if (cpart == 1) {
        #pragma unroll
        for (int s = 0; s < 2; s++) pr[4 + s][d] = q2[s];
    }
    __syncthreads();
    if (cpart == 0) {
        #pragma unroll
        for (int s = 0; s < 2; s++)
            g_q[(size_t)(b * SLOTS + sbase + s) * DDIM + d] = q2[s] + pr[4 + s][d];
    }
}

// ---------------- host launcher ----------------
extern "C" void kernel_launch(void* const* d_in, const int* in_sizes, int n_in,
                              void* d_out, int out_size) {
    const float* x        = (const float*)d_in[0];
    const float* slots_mu = (const float*)d_in[1];
    const float* ln_in_g  = (const float*)d_in[2];
    const float* ln_in_b  = (const float*)d_in[3];
    const float* wk       = (const float*)d_in[4];
    const float* wv       = (const float*)d_in[5];
    const float* ln_s_g   = (const float*)d_in[6];
    const float* ln_s_b   = (const float*)d_in[7];
    const float* wq       = (const float*)d_in[8];
    const float* gru_wih  = (const float*)d_in[9];
    const float* gru_whh  = (const float*)d_in[10];
    const float* gru_bih  = (const float*)d_in[11];
    const float* gru_bhh  = (const float*)d_in[12];
    const float* ln_m_g   = (const float*)d_in[13];
    const float* ln_m_b   = (const float*)d_in[14];
    const float* mlp_w1   = (const float*)d_in[15];
    const float* mlp_b1   = (const float*)d_in[16];
    const float* mlp_w2   = (const float*)d_in[17];
    const float* mlp_b2   = (const float*)d_in[18];

    float* out = (float*)d_out;
    float* out_slots = nullptr;
    float* out_attn  = nullptr;
    const int SLOTS_SZ = BATCH * SLOTS * DDIM;
    const int ATTN_SZ  = BATCH * NPOS * SLOTS;
    if (out_size >= SLOTS_SZ + ATTN_SZ) { out_slots = out; out_attn = out + SLOTS_SZ; }
    else if (out_size == ATTN_SZ)       { out_attn = out; }
    else                                { out_slots = out; }

    k_prep<<<2304, 256>>>(slots_mu, wk, wv, wq, gru_wih, gru_whh, mlp_w1, mlp_w2);
    k_ln_in<<<dim3(32, 64), 256>>>(x, ln_in_g, ln_in_b, ln_s_g, ln_s_b);
    k_gemm_kv_mma<<<dim3(4, 512), 256>>>();

    for (int it = 0; it < NITER; it++) {
        k_attn<<<dim3(BATCH, NCHUNK), 256>>>((it == NITER - 1) ? out_attn : nullptr,
                                             (it == 0) ? 1 : 0);
        k_slot_update<<<dim3(64, 4), 512>>>(gru_bih, gru_bhh,
                                            ln_m_g, ln_m_b, mlp_b1, mlp_b2,
                                            ln_s_g, ln_s_b,
                                            out_slots, (it == NITER - 1) ? 1 : 0,
                                            (it < NITER - 1) ? 1 : 0);
    }
}

// round 15
// speedup vs baseline: 1.0290x; 1.0290x over previous
#include <cuda_runtime.h>
#include <cuda_fp16.h>
#include <stdint.h>
#include <math.h>

#define BATCH 64
#define CDIM  256
#define NPOS  1024
#define SLOTS 8
#define DDIM  256
#define NITER 3
#define LN_EPS 1e-5f
#define ATT_SCALE 0.0625f   // D^-0.5
#define NCHUNK 32           // attention n-chunks (32 rows each)
#define CPB   4             // chunks per attn block
#define KPAD  (DDIM + 8)    // fp16 smem row padding: 528B rows (16B-aligned)
#define QPAD  (DDIM + 4)    // fp32 smem row padding

// ---------------- device scratch ----------------
__device__ __half g_xh[BATCH * NPOS * CDIM];         // fp16 LN(x)
__device__ __half g_wcat[512 * CDIM];                // [n][c] fp16 (wk rows then wv rows)
__device__ __half g_kh[BATCH * NPOS * DDIM];         // fp16 k
__device__ __half g_vh[BATCH * NPOS * DDIM];         // fp16 v
__device__ float g_slots[BATCH * SLOTS * DDIM];
__device__ float g_q    [BATCH * SLOTS * DDIM];
__device__ __half g_upd [NCHUNK * BATCH * SLOTS * DDIM];  // fp16 partials
// fp16 transposed weights [c][d]
__device__ __half g_wqTh [CDIM * DDIM];
__device__ __half g_w1Th [DDIM * DDIM];
__device__ __half g_w2Th [DDIM * DDIM];
__device__ __half g_wihTh[DDIM * 3 * DDIM];
__device__ __half g_whhTh[DDIM * 3 * DDIM];

// ---------------- helpers ----------------
__device__ __forceinline__ void cp16(void* s, const void* g) {
    unsigned sa = (unsigned)__cvta_generic_to_shared(s);
    asm volatile("cp.async.cg.shared.global [%0], [%1], 16;\n" :: "r"(sa), "l"(g));
}
__device__ __forceinline__ void cp_commit() { asm volatile("cp.async.commit_group;\n"); }
template<int N> __device__ __forceinline__ void cp_wait() {
    asm volatile("cp.async.wait_group %0;\n" :: "n"(N));
}
__device__ __forceinline__ uint4 ldm4(const void* p) {
    uint4 r;
    unsigned a = (unsigned)__cvta_generic_to_shared(p);
    asm volatile("ldmatrix.sync.aligned.m8n8.x4.shared.b16 {%0,%1,%2,%3}, [%4];"
                 : "=r"(r.x), "=r"(r.y), "=r"(r.z), "=r"(r.w) : "r"(a));
    return r;
}

// ---------------- one-time prep ----------------
__global__ void k_prep(const float* __restrict__ mu,
                       const float* __restrict__ wk, const float* __restrict__ wv,
                       const float* __restrict__ wq, const float* __restrict__ wih,
                       const float* __restrict__ whh, const float* __restrict__ w1,
                       const float* __restrict__ w2) {
    int i = blockIdx.x * 256 + threadIdx.x;
    if (i < 131072) {
        g_slots[i] = mu[i & (SLOTS * DDIM - 1)];
        float w = (i < 65536) ? wk[i] : wv[i - 65536];
        g_wcat[i] = __float2half(w);
    }
    if (i < 65536) {
        int d = i >> 8, c = i & 255;
        g_wqTh[c * 256 + d] = __float2half(wq[i]);
    } else if (i < 131072) {
        int j = i - 65536; int d = j >> 8; int c = j & 255;
        g_w1Th[c * 256 + d] = __float2half(w1[j]);
    } else if (i < 196608) {
        int j = i - 131072; int d = j >> 8; int c = j & 255;
        g_w2Th[c * 256 + d] = __float2half(w2[j]);
    } else if (i < 393216) {
        int j = i - 196608; int g = j >> 8; int c = j & 255;
        g_wihTh[c * 768 + g] = __float2half(wih[j]);
    } else if (i < 589824) {
        int j = i - 393216; int g = j >> 8; int c = j & 255;
        g_whhTh[c * 768 + g] = __float2half(whh[j]);
    }
}

// ---------------- transpose + input LayerNorm -> fp16 (+ fused iter-0 qproj) ----------------
__global__ void k_ln_in(const float* __restrict__ x,
                        const float* __restrict__ gam,
                        const float* __restrict__ bet,
                        const float* __restrict__ slg,
                        const float* __restrict__ slb) {
    __shared__ float tile[CDIM][33];
    __shared__ float mu_s[32], rs_s[32];
    int b  = blockIdx.y;
    int n0 = blockIdx.x * 32;
    int tid = threadIdx.x;
    const float* xb = x + (size_t)b * CDIM * NPOS;

    for (int i = tid; i < CDIM * 32; i += 256) {
        int c = i >> 5, n = i & 31;
        tile[c][n] = xb[c * NPOS + n0 + n];
    }
    __syncthreads();

    int warp = tid >> 5, lane = tid & 31;
    for (int col = warp; col < 32; col += 8) {
        float s = 0.f, s2 = 0.f;
        #pragma unroll
        for (int c = lane; c < CDIM; c += 32) {
            float v = tile[c][col];
            s += v; s2 += v * v;
        }
        #pragma unroll
        for (int o = 16; o; o >>= 1) {
            s  += __shfl_xor_sync(0xffffffffu, s,  o);
            s2 += __shfl_xor_sync(0xffffffffu, s2, o);
        }
        if (lane == 0) {
            float m   = s * (1.f / CDIM);
            float var = s2 * (1.f / CDIM) - m * m;
            mu_s[col] = m;
            rs_s[col] = rsqrtf(var + LN_EPS);
        }
    }
    __syncthreads();

    float gg = gam[tid], bb = bet[tid];
    size_t base = ((size_t)b * NPOS + n0) * CDIM + tid;
    #pragma unroll 8
    for (int n = 0; n < 32; n++) {
        float v = (tile[tid][n] - mu_s[n]) * rs_s[n] * gg + bb;
        g_xh[base + (size_t)n * CDIM] = __float2half(v);
    }

    // fused iter-0 q projection (4 early blocks): q = LN_s(slots_mu) @ wq^T into g_q[batch 0]
    if (blockIdx.x != 0 || blockIdx.y >= 4) return;
    int dq = blockIdx.y;
    __syncthreads();
    float* bufa = &tile[0][0];
    float (*sn)[DDIM] = (float(*)[DDIM])bufa;
    float (*part)[SLOTS][64] = (float(*)[SLOTS][64])(bufa + 2048);

    {
        int s = warp;
        const float* row = g_slots + (size_t)s * DDIM;
        float v[8]; float sum = 0.f, sq = 0.f;
        #pragma unroll
        for (int j = 0; j < 8; j++) {
            v[j] = row[lane + 32 * j];
            sum += v[j]; sq += v[j] * v[j];
        }
        #pragma unroll
        for (int o = 16; o; o >>= 1) {
            sum += __shfl_xor_sync(0xffffffffu, sum, o);
            sq  += __shfl_xor_sync(0xffffffffu, sq,  o);
        }
        float m = sum * (1.f / DDIM);
        float r = rsqrtf(sq * (1.f / DDIM) - m * m + LN_EPS);
        #pragma unroll
        for (int j = 0; j < 8; j++) {
            int c = lane + 32 * j;
            sn[s][c] = (v[j] - m) * r * slg[c] + slb[c];
        }
    }
    __syncthreads();

    int dd = tid & 63, pp = tid >> 6;
    int d  = dq * 64 + dd;
    float acc[SLOTS];
    #pragma unroll
    for (int s = 0; s < SLOTS; s++) acc[s] = 0.f;
    #pragma unroll 8
    for (int cc = 0; cc < 64; cc++) {
        int c = pp * 64 + cc;
        float ww = __half2float(g_wqTh[c * DDIM + d]);
        #pragma unroll
        for (int s = 0; s < SLOTS; s++) acc[s] = fmaf(sn[s][c], ww, acc[s]);
    }
    #pragma unroll
    for (int s = 0; s < SLOTS; s++) part[pp][s][dd] = acc[s];
    __syncthreads();

    for (int o = tid; o < SLOTS * 64; o += 256) {
        int s = o >> 6, dd2 = o & 63;
        float v = part[0][s][dd2] + part[1][s][dd2] + part[2][s][dd2] + part[3][s][dd2];
        g_q[(size_t)s * DDIM + dq * 64 + dd2] = v;
    }
}

// ---------------- big GEMM: fp16, K=256, 3-stage cp.async + ldmatrix + mma ----------------
__global__ void __launch_bounds__(256, 2) k_gemm_kv_mma() {
    __shared__ __half As[3][128][40];
    __shared__ __half Bs[3][128][40];
    int n0 = blockIdx.x * 128;
    int m0 = blockIdx.y * 128;
    int tid = threadIdx.x, lane = tid & 31, warp = tid >> 5;
    int wm = (warp & 3) * 32, wn = (warp >> 2) * 64;
    __half* Out = (n0 < 256) ? g_kh : g_vh;
    int ncol0 = n0 & 255;
    int lr = tid >> 1, lc = (tid & 1) * 8;

    int g8 = lane >> 3, l8 = lane & 7;
    int aro = l8 + (g8 & 1) * 8, aco = (g8 >> 1) * 8;
    int bro = l8 + (g8 >> 1) * 8, bco = (g8 & 1) * 8;

    float acc[2][8][4];
    #pragma unroll
    for (int i = 0; i < 2; i++)
        #pragma unroll
        for (int j = 0; j < 8; j++)
            #pragma unroll
            for (int q = 0; q < 4; q++) acc[i][j][q] = 0.f;

    auto issue = [&](int kti, int buf) {
        int kt = kti * 32;
        const __half* ga = g_xh + (size_t)(m0 + lr) * CDIM + kt + lc;
        const __half* gb = g_wcat + (size_t)(n0 + lr) * CDIM + kt + lc;
        cp16(&As[buf][lr][lc],      ga);
        cp16(&As[buf][lr][lc + 16], ga + 16);
        cp16(&Bs[buf][lr][lc],      gb);
        cp16(&Bs[buf][lr][lc + 16], gb + 16);
    };

    issue(0, 0); cp_commit();
    issue(1, 1); cp_commit();

    for (int i = 0; i < 8; i++) {
        if (i < 7) cp_wait<1>(); else cp_wait<0>();
        __syncthreads();
        if (i < 6) { issue(i + 2, (i + 2) % 3); cp_commit(); }
        int buf = i % 3;

        #pragma unroll
        for (int k16 = 0; k16 < 32; k16 += 16) {
            uint4 av[2], bv[4];
            #pragma unroll
            for (int im = 0; im < 2; im++)
                av[im] = ldm4(&As[buf][wm + im * 16 + aro][k16 + aco]);
            #pragma unroll
            for (int t = 0; t < 4; t++)
                bv[t] = ldm4(&Bs[buf][wn + t * 16 + bro][k16 + bco]);

            #pragma unroll
            for (int im = 0; im < 2; im++)
                #pragma unroll
                for (int t = 0; t < 4; t++) {
                    asm volatile(
                        "mma.sync.aligned.m16n8k16.row.col.f32.f16.f16.f32 "
                        "{%0,%1,%2,%3}, {%4,%5,%6,%7}, {%8,%9}, {%0,%1,%2,%3};\n"
                        : "+f"(acc[im][2*t][0]), "+f"(acc[im][2*t][1]),
                          "+f"(acc[im][2*t][2]), "+f"(acc[im][2*t][3])
                        : "r"(av[im].x), "r"(av[im].y), "r"(av[im].z), "r"(av[im].w),
                          "r"(bv[t].x), "r"(bv[t].y));
                    asm volatile(
                        "mma.sync.aligned.m16n8k16.row.col.f32.f16.f16.f32 "
                        "{%0,%1,%2,%3}, {%4,%5,%6,%7}, {%8,%9}, {%0,%1,%2,%3};\n"
                        : "+f"(acc[im][2*t+1][0]), "+f"(acc[im][2*t+1][1]),
                          "+f"(acc[im][2*t+1][2]), "+f"(acc[im][2*t+1][3])
                        : "r"(av[im].x), "r"(av[im].y), "r"(av[im].z), "r"(av[im].w),
                          "r"(bv[t].z), "r"(bv[t].w));
                }
        }
        __syncthreads();
    }

    #pragma unroll
    for (int im = 0; im < 2; im++)
        #pragma unroll
        for (int jn = 0; jn < 8; jn++) {
            int row = m0 + wm + im * 16 + (lane >> 2);
            int col = ncol0 + wn + jn * 8 + (lane & 3) * 2;
            __half* p = Out + (size_t)row * DDIM + col;
            *(__half2*)p = __floats2half2_rn(acc[im][jn][0], acc[im][jn][1]);
            *(__half2*)(p + 8 * DDIM) = __floats2half2_rn(acc[im][jn][2], acc[im][jn][3]);
        }
}

// ---------------- attention: pipelined 4 chunks/block, double-buffered cp.async ----------------
__global__ void __launch_bounds__(256) k_attn(float* __restrict__ attn_out, int q_bcast) {
    int b = blockIdx.x, cg = blockIdx.y;          // cg: chunk-group (4 chunks)
    __shared__ __half ksm[2][32][KPAD];           // 2 x 16.5KB
    __shared__ __half vsm[2][32][KPAD];           // 2 x 16.5KB
    __shared__ float  qs[SLOTS][QPAD];            // 8.3KB
    __shared__ float  as_[32][SLOTS];
    int tid = threadIdx.x;

    auto issue_chunk = [&](int c4, int buf) {
        int n0 = (cg * CPB + c4) * 32;
        const __half* kg = g_kh + (size_t)(b * NPOS + n0) * DDIM;
        const __half* vg = g_vh + (size_t)(b * NPOS + n0) * DDIM;
        #pragma unroll
        for (int i = 0; i < 4; i++) {
            int idx = tid + i * 256;              // 0..1023 = 32 rows x 32 segs
            int row = idx >> 5, seg = idx & 31;
            cp16(&ksm[buf][row][seg * 8], kg + (size_t)row * DDIM + seg * 8);
            cp16(&vsm[buf][row][seg * 8], vg + (size_t)row * DDIM + seg * 8);
        }
        cp_commit();
    };

    {   // load q
        int qb = q_bcast ? 0 : b;
        const float* qsrc = g_q + (size_t)qb * SLOTS * DDIM;
        #pragma unroll
        for (int i = 0; i < 8; i++) {
            int idx = tid + i * 256;
            qs[idx >> 8][idx & 255] = qsrc[idx];
        }
    }
    issue_chunk(0, 0);

    for (int c4 = 0; c4 < CPB; c4++) {
        int buf = c4 & 1;
        if (c4 < CPB - 1) issue_chunk(c4 + 1, buf ^ 1);
        if (c4 < CPB - 1) cp_wait<1>(); else cp_wait<0>();
        __syncthreads();

        int ch = cg * CPB + c4;
        int n0 = ch * 32;

        // logits: thread-per-(row,slot), float4 smem reads
        {
            int r = tid >> 3, s = tid & 7;
            const float4* krow = (const float4*)&ksm[buf][r][0];
            const float4* qrow = (const float4*)&qs[s][0];
            float acc = 0.f;
            #pragma unroll 8
            for (int i = 0; i < 32; i++) {
                float4 kq = krow[i];
                __half2* kh = (__half2*)&kq;
                float4 q0 = qrow[i * 2], q1 = qrow[i * 2 + 1];
                float2 k0 = __half22float2(kh[0]), k1 = __half22float2(kh[1]);
                float2 k2 = __half22float2(kh[2]), k3 = __half22float2(kh[3]);
                acc += k0.x*q0.x + k0.y*q0.y + k1.x*q0.z + k1.y*q0.w
                     + k2.x*q1.x + k2.y*q1.y + k3.x*q1.z + k3.y*q1.w;
            }
            float logit = acc * ATT_SCALE;
            float mx = logit;
            #pragma unroll
            for (int m = 1; m < 8; m <<= 1)
                mx = fmaxf(mx, __shfl_xor_sync(0xffffffffu, mx, m));
            float e = expf(logit - mx);
            float ssum = e;
            #pragma unroll
            for (int m = 1; m < 8; m <<= 1)
                ssum += __shfl_xor_sync(0xffffffffu, ssum, m);
            float a = e / ssum;
            as_[r][s] = a;
            if (attn_out)
                attn_out[(size_t)(b * NPOS + n0 + r) * SLOTS + s] = a;
        }
        __syncthreads();

        // partial updates: thread owns channel c
        int c = tid;
        float acc[SLOTS];
        #pragma unroll
        for (int s = 0; s < SLOTS; s++) acc[s] = 0.f;
        #pragma unroll 8
        for (int nn = 0; nn < 32; nn++) {
            float vv = __half2float(vsm[buf][nn][c]);
            #pragma unroll
            for (int s = 0; s < SLOTS; s++) acc[s] = fmaf(as_[nn][s], vv, acc[s]);
        }
        __half* up = g_upd + (size_t)((ch * BATCH + b) * SLOTS) * DDIM + c;
        #pragma unroll
        for (int s = 0; s < SLOTS; s++) up[(size_t)s * DDIM] = __float2half(acc[s]);
        __syncthreads();
    }
}

// ---------------- slot update: R13 version — grid (64,2), 4 slots/block, 512 threads ----------------
__global__ void __launch_bounds__(512) k_slot_update(
        const float* __restrict__ bih, const float* __restrict__ bhh,
        const float* __restrict__ lg,  const float* __restrict__ lb,
        const float* __restrict__ b1,  const float* __restrict__ b2,
        const float* __restrict__ slg, const float* __restrict__ slb,
        float* __restrict__ out_slots, int write_out, int write_q) {
    int b = blockIdx.x, half = blockIdx.y;
    __shared__ float u [4][DDIM];
    __shared__ float h [4][DDIM];
    __shared__ float nh[4][DDIM];
    __shared__ float hm[4][DDIM];
    __shared__ float pr[24][DDIM];
    int tid = threadIdx.x;
    int d = tid & 255, cpart = tid >> 8;
    int c0 = cpart * 128;
    int sbase = half * 4;

    for (int i = tid; i < 4 * DDIM; i += 512) {
        int s = i >> 8, c = i & 255;
        float a = 0.f;
        #pragma unroll
        for (int chn = 0; chn < NCHUNK; chn++)
            a += __half2float(g_upd[(size_t)((chn * BATCH + b) * SLOTS + sbase + s) * DDIM + c]);
        u[s][c] = a;
        h[s][c] = g_slots[(size_t)(b * SLOTS + sbase + s) * DDIM + c];
    }
    __syncthreads();

    float ir[4] = {0,0,0,0}, iz[4] = {0,0,0,0}, in_[4] = {0,0,0,0};
    float hr[4] = {0,0,0,0}, hz[4] = {0,0,0,0}, hn_[4] = {0,0,0,0};
    #pragma unroll 4
    for (int cc = 0; cc < 128; cc++) {
        int c = c0 + cc;
        float a0 = __half2float(g_wihTh[c * 768 + d]);
        float a1 = __half2float(g_wihTh[c * 768 + 256 + d]);
        float a2 = __half2float(g_wihTh[c * 768 + 512 + d]);
        float c0w = __half2float(g_whhTh[c * 768 + d]);
        float c1w = __half2float(g_whhTh[c * 768 + 256 + d]);
        float c2w = __half2float(g_whhTh[c * 768 + 512 + d]);
        #pragma unroll
        for (int s = 0; s < 4; s++) {
            float uu = u[s][c], hh = h[s][c];
            ir[s] = fmaf(a0, uu, ir[s]); iz[s] = fmaf(a1, uu, iz[s]); in_[s] = fmaf(a2, uu, in_[s]);
            hr[s] = fmaf(c0w, hh, hr[s]); hz[s] = fmaf(c1w, hh, hz[s]); hn_[s] = fmaf(c2w, hh, hn_[s]);
        }
    }
    if (cpart == 1) {
        #pragma unroll
        for (int s = 0; s < 4; s++) {
            pr[s][d]      = ir[s];  pr[4 + s][d]  = iz[s];  pr[8 + s][d]  = in_[s];
            pr[12 + s][d] = hr[s];  pr[16 + s][d] = hz[s];  pr[20 + s][d] = hn_[s];
        }
    }
    __syncthreads();
    if (cpart == 0) {
        float bir = bih[d], biz = bih[DDIM + d], bin = bih[2 * DDIM + d];
        float bhr = bhh[d], bhz = bhh[DDIM + d], bhn = bhh[2 * DDIM + d];
        #pragma unroll
        for (int s = 0; s < 4; s++) {
            float rI = ir[s] + pr[s][d],      zI = iz[s] + pr[4 + s][d],  nI = in_[s] + pr[8 + s][d];
            float rH = hr[s] + pr[12 + s][d], zH = hz[s] + pr[16 + s][d], nH = hn_[s] + pr[20 + s][d];
            float r = 1.f / (1.f + expf(-(rI + bir + rH + bhr)));
            float z = 1.f / (1.f + expf(-(zI + biz + zH + bhz)));
            float n = tanhf(nI + bin + r * (nH + bhn));
            nh[s][d] = (1.f - z) * n + z * h[s][d];
        }
    }
    __syncthreads();

    int warp = tid >> 5, lane = tid & 31;
    if (warp < 4) {
        int s = warp;
        float v[8]; float sum = 0.f, sq = 0.f;
        #pragma unroll
        for (int j = 0; j < 8; j++) {
            v[j] = nh[s][lane + 32 * j];
            sum += v[j]; sq += v[j] * v[j];
        }
        #pragma unroll
        for (int o = 16; o; o >>= 1) {
            sum += __shfl_xor_sync(0xffffffffu, sum, o);
            sq  += __shfl_xor_sync(0xffffffffu, sq,  o);
        }
        float m = sum * (1.f / DDIM);
        float rs = rsqrtf(sq * (1.f / DDIM) - m * m + LN_EPS);
        #pragma unroll
        for (int j = 0; j < 8; j++) {
            int c = lane + 32 * j;
            u[s][c] = (v[j] - m) * rs * lg[c] + lb[c];
        }
    }
    __syncthreads();

    float m4[4] = {0,0,0,0};
    #pragma unroll 4
    for (int cc = 0; cc < 128; cc++) {
        int c = c0 + cc;
        float ww = __half2float(g_w1Th[c * DDIM + d]);
        #pragma unroll
        for (int s = 0; s < 4; s++) m4[s] = fmaf(u[s][c], ww, m4[s]);
    }
    if (cpart == 1) {
        #pragma unroll
        for (int s = 0; s < 4; s++) pr[s][d] = m4[s];
    }
    __syncthreads();
    if (cpart == 0) {
        float bb1 = b1[d];
        #pragma unroll
        for (int s = 0; s < 4; s++) hm[s][d] = fmaxf(m4[s] + pr[s][d] + bb1, 0.f);
    }
    __syncthreads();

    float o4[4] = {0,0,0,0};
    #pragma unroll 4
    for (int cc = 0; cc < 128; cc++) {
        int c = c0 + cc;
        float ww = __half2float(g_w2Th[c * DDIM + d]);
        #pragma unroll
        for (int s = 0; s < 4; s++) o4[s] = fmaf(hm[s][c], ww, o4[s]);
    }
    if (cpart == 1) {
        #pragma unroll
        for (int s = 0; s < 4; s++) pr[4 + s][d] = o4[s];
    }
    __syncthreads();
    if (cpart == 0) {
        float bb2 = b2[d];
        #pragma unroll
        for (int s = 0; s < 4; s++) {
            float res = nh[s][d] + o4[s] + pr[4 + s][d] + bb2;
            h[s][d] = res;
            g_slots[(size_t)(b * SLOTS + sbase + s) * DDIM + d] = res;
            if (write_out && out_slots)
                out_slots[(size_t)(b * SLOTS + sbase + s) * DDIM + d] = res;
        }
    }
    __syncthreads();

    if (!write_q) return;

    if (warp < 4) {
        int s = warp;
        float v[8]; float sum = 0.f, sq = 0.f;
        #pragma unroll
        for (int j = 0; j < 8; j++) {
            v[j] = h[s][lane + 32 * j];
            sum += v[j]; sq += v[j] * v[j];
        }
        #pragma unroll
        for (int o = 16; o; o >>= 1) {
            sum += __shfl_xor_sync(0xffffffffu, sum, o);
            sq  += __shfl_xor_sync(0xffffffffu, sq,  o);
        }
        float m = sum * (1.f / DDIM);
        float rs = rsqrtf(sq * (1.f / DDIM) - m * m + LN_EPS);
        #pragma unroll
        for (int j = 0; j < 8; j++) {
            int c = lane + 32 * j;
            u[s][c] = (v[j] - m) * rs * slg[c] + slb[c];
        }
    }
    __syncthreads();
    float q4[4] = {0,0,0,0};
    #pragma unroll 4
    for (int cc = 0; cc < 128; cc++) {
        int c = c0 + cc;
        float ww = __half2float(g_wqTh[c * DDIM + d]);
        #pragma unroll
        for (int s = 0; s < 4; s++) q4[s] = fmaf(u[s][c], ww, q4[s]);
    }
    if (cpart == 1) {
        #pragma unroll
        for (int s = 0; s < 4; s++) pr[8 + s][d] = q4[s];
    }
    __syncthreads();
    if (cpart == 0) {
        #pragma unroll
        for (int s = 0; s < 4; s++)
            g_q[(size_t)(b * SLOTS + sbase + s) * DDIM + d] = q4[s] + pr[8 + s][d];
    }
}

// ---------------- host launcher ----------------
extern "C" void kernel_launch(void* const* d_in, const int* in_sizes, int n_in,
                              void* d_out, int out_size) {
    const float* x        = (const float*)d_in[0];
    const float* slots_mu = (const float*)d_in[1];
    const float* ln_in_g  = (const float*)d_in[2];
    const float* ln_in_b  = (const float*)d_in[3];
    const float* wk       = (const float*)d_in[4];
    const float* wv       = (const float*)d_in[5];
    const float* ln_s_g   = (const float*)d_in[6];
    const float* ln_s_b   = (const float*)d_in[7];
    const float* wq       = (const float*)d_in[8];
    const float* gru_wih  = (const float*)d_in[9];
    const float* gru_whh  = (const float*)d_in[10];
    const float* gru_bih  = (const float*)d_in[11];
    const float* gru_bhh  = (const float*)d_in[12];
    const float* ln_m_g   = (const float*)d_in[13];
    const float* ln_m_b   = (const float*)d_in[14];
    const float* mlp_w1   = (const float*)d_in[15];
    const float* mlp_b1   = (const float*)d_in[16];
    const float* mlp_w2   = (const float*)d_in[17];
    const float* mlp_b2   = (const float*)d_in[18];

    float* out = (float*)d_out;
    float* out_slots = nullptr;
    float* out_attn  = nullptr;
    const int SLOTS_SZ = BATCH * SLOTS * DDIM;
    const int ATTN_SZ  = BATCH * NPOS * SLOTS;
    if (out_size >= SLOTS_SZ + ATTN_SZ) { out_slots = out; out_attn = out + SLOTS_SZ; }
    else if (out_size == ATTN_SZ)       { out_attn = out; }
    else                                { out_slots = out; }

    k_prep<<<2304, 256>>>(slots_mu, wk, wv, wq, gru_wih, gru_whh, mlp_w1, mlp_w2);
    k_ln_in<<<dim3(32, 64), 256>>>(x, ln_in_g, ln_in_b, ln_s_g, ln_s_b);
    k_gemm_kv_mma<<<dim3(4, 512), 256>>>();

    for (int it = 0; it < NITER; it++) {
        k_attn<<<dim3(BATCH, NCHUNK / CPB), 256>>>((it == NITER - 1) ? out_attn : nullptr,
                                                   (it == 0) ? 1 : 0);
        k_slot_update<<<dim3(64, 2), 512>>>(gru_bih, gru_bhh,
                                            ln_m_g, ln_m_b, mlp_b1, mlp_b2,
                                            ln_s_g, ln_s_b,
                                            out_slots, (it == NITER - 1) ? 1 : 0,
                                            (it < NITER - 1) ? 1 : 0);
    }
}

// round 16
// speedup vs baseline: 1.0787x; 1.0483x over previous
#include <cuda_runtime.h>
#include <cuda_fp16.h>
#include <stdint.h>
#include <math.h>

#define BATCH 64
#define CDIM  256
#define NPOS  1024
#define SLOTS 8
#define DDIM  256
#define NITER 3
#define LN_EPS 1e-5f
#define ATT_SCALE 0.0625f   // D^-0.5
#define NCHUNK 32           // attention n-chunks (32 rows each)
#define KPAD  (DDIM + 8)    // fp16 smem row padding: 528B rows (16B-aligned)
#define QPAD  (DDIM + 4)    // fp32 smem row padding

// ---------------- device scratch ----------------
__device__ __half g_xh[BATCH * NPOS * CDIM];         // fp16 LN(x)
__device__ __half g_wcat[512 * CDIM];                // [n][c] fp16 (wk rows then wv rows)
__device__ __half g_kh[BATCH * NPOS * DDIM];         // fp16 k
__device__ __half g_vh[BATCH * NPOS * DDIM];         // fp16 v
__device__ float g_slots[BATCH * SLOTS * DDIM];
__device__ float g_q    [BATCH * SLOTS * DDIM];
__device__ __half g_upd [NCHUNK * BATCH * SLOTS * DDIM];  // fp16 partials
// fp16 transposed weights [c][d]
__device__ __half g_wqTh [CDIM * DDIM];
__device__ __half g_w1Th [DDIM * DDIM];
__device__ __half g_w2Th [DDIM * DDIM];
__device__ __half g_wihTh[DDIM * 3 * DDIM];
__device__ __half g_whhTh[DDIM * 3 * DDIM];

// ---------------- helpers ----------------
__device__ __forceinline__ void cp16(void* s, const void* g) {
    unsigned sa = (unsigned)__cvta_generic_to_shared(s);
    asm volatile("cp.async.cg.shared.global [%0], [%1], 16;\n" :: "r"(sa), "l"(g));
}
__device__ __forceinline__ void cp_commit() { asm volatile("cp.async.commit_group;\n"); }
template<int N> __device__ __forceinline__ void cp_wait() {
    asm volatile("cp.async.wait_group %0;\n" :: "n"(N));
}
__device__ __forceinline__ uint4 ldm4(const void* p) {
    uint4 r;
    unsigned a = (unsigned)__cvta_generic_to_shared(p);
    asm volatile("ldmatrix.sync.aligned.m8n8.x4.shared.b16 {%0,%1,%2,%3}, [%4];"
                 : "=r"(r.x), "=r"(r.y), "=r"(r.z), "=r"(r.w) : "r"(a));
    return r;
}

// ---------------- one-time prep ----------------
__global__ void k_prep(const float* __restrict__ mu,
                       const float* __restrict__ wk, const float* __restrict__ wv,
                       const float* __restrict__ wq, const float* __restrict__ wih,
                       const float* __restrict__ whh, const float* __restrict__ w1,
                       const float* __restrict__ w2) {
    int i = blockIdx.x * 256 + threadIdx.x;
    if (i < 131072) {
        g_slots[i] = mu[i & (SLOTS * DDIM - 1)];
        float w = (i < 65536) ? wk[i] : wv[i - 65536];
        g_wcat[i] = __float2half(w);
    }
    if (i < 65536) {
        int d = i >> 8, c = i & 255;
        g_wqTh[c * 256 + d] = __float2half(wq[i]);
    } else if (i < 131072) {
        int j = i - 65536; int d = j >> 8; int c = j & 255;
        g_w1Th[c * 256 + d] = __float2half(w1[j]);
    } else if (i < 196608) {
        int j = i - 131072; int d = j >> 8; int c = j & 255;
        g_w2Th[c * 256 + d] = __float2half(w2[j]);
    } else if (i < 393216) {
        int j = i - 196608; int g = j >> 8; int c = j & 255;
        g_wihTh[c * 768 + g] = __float2half(wih[j]);
    } else if (i < 589824) {
        int j = i - 393216; int g = j >> 8; int c = j & 255;
        g_whhTh[c * 768 + g] = __float2half(whh[j]);
    }
}

// ---------------- transpose + input LayerNorm -> fp16 (+ fused iter-0 qproj) ----------------
__global__ void k_ln_in(const float* __restrict__ x,
                        const float* __restrict__ gam,
                        const float* __restrict__ bet,
                        const float* __restrict__ slg,
                        const float* __restrict__ slb) {
    __shared__ float tile[CDIM][33];
    __shared__ float mu_s[32], rs_s[32];
    int b  = blockIdx.y;
    int n0 = blockIdx.x * 32;
    int tid = threadIdx.x;
    const float* xb = x + (size_t)b * CDIM * NPOS;

    for (int i = tid; i < CDIM * 32; i += 256) {
        int c = i >> 5, n = i & 31;
        tile[c][n] = xb[c * NPOS + n0 + n];
    }
    __syncthreads();

    int warp = tid >> 5, lane = tid & 31;
    for (int col = warp; col < 32; col += 8) {
        float s = 0.f, s2 = 0.f;
        #pragma unroll
        for (int c = lane; c < CDIM; c += 32) {
            float v = tile[c][col];
            s += v; s2 += v * v;
        }
        #pragma unroll
        for (int o = 16; o; o >>= 1) {
            s  += __shfl_xor_sync(0xffffffffu, s,  o);
            s2 += __shfl_xor_sync(0xffffffffu, s2, o);
        }
        if (lane == 0) {
            float m   = s * (1.f / CDIM);
            float var = s2 * (1.f / CDIM) - m * m;
            mu_s[col] = m;
            rs_s[col] = rsqrtf(var + LN_EPS);
        }
    }
    __syncthreads();

    float gg = gam[tid], bb = bet[tid];
    size_t base = ((size_t)b * NPOS + n0) * CDIM + tid;
    #pragma unroll 8
    for (int n = 0; n < 32; n++) {
        float v = (tile[tid][n] - mu_s[n]) * rs_s[n] * gg + bb;
        g_xh[base + (size_t)n * CDIM] = __float2half(v);
    }

    // fused iter-0 q projection (4 early blocks): q = LN_s(slots_mu) @ wq^T into g_q[batch 0]
    if (blockIdx.x != 0 || blockIdx.y >= 4) return;
    int dq = blockIdx.y;
    __syncthreads();
    float* bufa = &tile[0][0];
    float (*sn)[DDIM] = (float(*)[DDIM])bufa;
    float (*part)[SLOTS][64] = (float(*)[SLOTS][64])(bufa + 2048);

    {
        int s = warp;
        const float* row = g_slots + (size_t)s * DDIM;
        float v[8]; float sum = 0.f, sq = 0.f;
        #pragma unroll
        for (int j = 0; j < 8; j++) {
            v[j] = row[lane + 32 * j];
            sum += v[j]; sq += v[j] * v[j];
        }
        #pragma unroll
        for (int o = 16; o; o >>= 1) {
            sum += __shfl_xor_sync(0xffffffffu, sum, o);
            sq  += __shfl_xor_sync(0xffffffffu, sq,  o);
        }
        float m = sum * (1.f / DDIM);
        float r = rsqrtf(sq * (1.f / DDIM) - m * m + LN_EPS);
        #pragma unroll
        for (int j = 0; j < 8; j++) {
            int c = lane + 32 * j;
            sn[s][c] = (v[j] - m) * r * slg[c] + slb[c];
        }
    }
    __syncthreads();

    int dd = tid & 63, pp = tid >> 6;
    int d  = dq * 64 + dd;
    float acc[SLOTS];
    #pragma unroll
    for (int s = 0; s < SLOTS; s++) acc[s] = 0.f;
    #pragma unroll 8
    for (int cc = 0; cc < 64; cc++) {
        int c = pp * 64 + cc;
        float ww = __half2float(g_wqTh[c * DDIM + d]);
        #pragma unroll
        for (int s = 0; s < SLOTS; s++) acc[s] = fmaf(sn[s][c], ww, acc[s]);
    }
    #pragma unroll
    for (int s = 0; s < SLOTS; s++) part[pp][s][dd] = acc[s];
    __syncthreads();

    for (int o = tid; o < SLOTS * 64; o += 256) {
        int s = o >> 6, dd2 = o & 63;
        float v = part[0][s][dd2] + part[1][s][dd2] + part[2][s][dd2] + part[3][s][dd2];
        g_q[(size_t)s * DDIM + dq * 64 + dd2] = v;
    }
}

// ---------------- big GEMM: 128x64 tiles, 8 warps of 32x32, 3-stage cp.async ----------------
// grid (8, 512): n-tile fast-varying -> 8 n-tiles of an m-strip share A via L2.
__global__ void __launch_bounds__(256, 4) k_gemm_kv_mma() {
    __shared__ __half As[3][128][40];
    __shared__ __half Bs[3][64][40];
    int n0 = blockIdx.x * 64;
    int m0 = blockIdx.y * 128;
    int tid = threadIdx.x, lane = tid & 31, warp = tid >> 5;
    int wm = (warp & 3) * 32, wn = (warp >> 2) * 32;
    __half* Out = (n0 < 256) ? g_kh : g_vh;
    int ncol0 = n0 & 255;

    int g8 = lane >> 3, l8 = lane & 7;
    int aro = l8 + (g8 & 1) * 8, aco = (g8 >> 1) * 8;
    int bro = l8 + (g8 >> 1) * 8, bco = (g8 & 1) * 8;

    float acc[2][4][4];
    #pragma unroll
    for (int i = 0; i < 2; i++)
        #pragma unroll
        for (int j = 0; j < 4; j++)
            #pragma unroll
            for (int q = 0; q < 4; q++) acc[i][j][q] = 0.f;

    // fill mapping: A 128 rows x 4 chunks (2 per thread), B 64 rows x 4 chunks (1 per thread)
    int alr = tid >> 1, alc = (tid & 1) * 16;     // A: two cp16 at alc, alc+8
    int blr = tid >> 2, blc = (tid & 3) * 8;      // B: one cp16

    auto issue = [&](int kti, int buf) {
        int kt = kti * 32;
        const __half* ga = g_xh + (size_t)(m0 + alr) * CDIM + kt + alc;
        const __half* gb = g_wcat + (size_t)(n0 + blr) * CDIM + kt + blc;
        cp16(&As[buf][alr][alc],     ga);
        cp16(&As[buf][alr][alc + 8], ga + 8);
        cp16(&Bs[buf][blr][blc],     gb);
    };

    issue(0, 0); cp_commit();
    issue(1, 1); cp_commit();

    for (int i = 0; i < 8; i++) {
        if (i < 7) cp_wait<1>(); else cp_wait<0>();
        __syncthreads();
        if (i < 6) { issue(i + 2, (i + 2) % 3); cp_commit(); }
        int buf = i % 3;

        #pragma unroll
        for (int k16 = 0; k16 < 32; k16 += 16) {
            uint4 av[2], bv[2];
            #pragma unroll
            for (int im = 0; im < 2; im++)
                av[im] = ldm4(&As[buf][wm + im * 16 + aro][k16 + aco]);
            #pragma unroll
            for (int t = 0; t < 2; t++)
                bv[t] = ldm4(&Bs[buf][wn + t * 16 + bro][k16 + bco]);

            #pragma unroll
            for (int im = 0; im < 2; im++)
                #pragma unroll
                for (int t = 0; t < 2; t++) {
                    asm volatile(
                        "mma.sync.aligned.m16n8k16.row.col.f32.f16.f16.f32 "
                        "{%0,%1,%2,%3}, {%4,%5,%6,%7}, {%8,%9}, {%0,%1,%2,%3};\n"
                        : "+f"(acc[im][2*t][0]), "+f"(acc[im][2*t][1]),
                          "+f"(acc[im][2*t][2]), "+f"(acc[im][2*t][3])
                        : "r"(av[im].x), "r"(av[im].y), "r"(av[im].z), "r"(av[im].w),
                          "r"(bv[t].x), "r"(bv[t].y));
                    asm volatile(
                        "mma.sync.aligned.m16n8k16.row.col.f32.f16.f16.f32 "
                        "{%0,%1,%2,%3}, {%4,%5,%6,%7}, {%8,%9}, {%0,%1,%2,%3};\n"
                        : "+f"(acc[im][2*t+1][0]), "+f"(acc[im][2*t+1][1]),
                          "+f"(acc[im][2*t+1][2]), "+f"(acc[im][2*t+1][3])
                        : "r"(av[im].x), "r"(av[im].y), "r"(av[im].z), "r"(av[im].w),
                          "r"(bv[t].z), "r"(bv[t].w));
                }
        }
        __syncthreads();
    }

    #pragma unroll
    for (int im = 0; im < 2; im++)
        #pragma unroll
        for (int jn = 0; jn < 4; jn++) {
            int row = m0 + wm + im * 16 + (lane >> 2);
            int col = ncol0 + wn + jn * 8 + (lane & 3) * 2;
            __half* p = Out + (size_t)row * DDIM + col;
            *(__half2*)p = __floats2half2_rn(acc[im][jn][0], acc[im][jn][1]);
            *(__half2*)(p + 8 * DDIM) = __floats2half2_rn(acc[im][jn][2], acc[im][jn][3]);
        }
}

// ---------------- attention: R13 config + cp.async fill ----------------
__global__ void __launch_bounds__(256) k_attn(float* __restrict__ attn_out, int q_bcast) {
    int b = blockIdx.x, ch = blockIdx.y;
    int n0 = ch * 32;
    __shared__ __half ksm[32][KPAD];
    __shared__ __half vsm[32][KPAD];
    __shared__ float  qs[SLOTS][QPAD];
    __shared__ float  as_[32][SLOTS];
    int tid = threadIdx.x;

    {   // k,v fill via cp.async (deep MLP, no reg round-trip)
        const __half* kg = g_kh + (size_t)(b * NPOS + n0) * DDIM;
        const __half* vg = g_vh + (size_t)(b * NPOS + n0) * DDIM;
        #pragma unroll
        for (int i = 0; i < 4; i++) {
            int idx = tid + i * 256;
            int row = idx >> 5, seg = idx & 31;
            cp16(&ksm[row][seg * 8], kg + (size_t)row * DDIM + seg * 8);
            cp16(&vsm[row][seg * 8], vg + (size_t)row * DDIM + seg * 8);
        }
        cp_commit();
    }
    {   // load q while k/v in flight
        int qb = q_bcast ? 0 : b;
        const float* qsrc = g_q + (size_t)qb * SLOTS * DDIM;
        #pragma unroll
        for (int i = 0; i < 8; i++) {
            int idx = tid + i * 256;
            qs[idx >> 8][idx & 255] = qsrc[idx];
        }
    }
    cp_wait<0>();
    __syncthreads();

    // logits: thread-per-(row,slot), float4 smem reads
    {
        int r = tid >> 3, s = tid & 7;
        const float4* krow = (const float4*)&ksm[r][0];
        const float4* qrow = (const float4*)&qs[s][0];
        float acc = 0.f;
        #pragma unroll 8
        for (int i = 0; i < 32; i++) {
            float4 kq = krow[i];
            __half2* kh = (__half2*)&kq;
            float4 q0 = qrow[i * 2], q1 = qrow[i * 2 + 1];
            float2 k0 = __half22float2(kh[0]), k1 = __half22float2(kh[1]);
            float2 k2 = __half22float2(kh[2]), k3 = __half22float2(kh[3]);
            acc += k0.x*q0.x + k0.y*q0.y + k1.x*q0.z + k1.y*q0.w
                 + k2.x*q1.x + k2.y*q1.y + k3.x*q1.z + k3.y*q1.w;
        }
        float logit = acc * ATT_SCALE;
        float mx = logit;
        #pragma unroll
        for (int m = 1; m < 8; m <<= 1)
            mx = fmaxf(mx, __shfl_xor_sync(0xffffffffu, mx, m));
        float e = expf(logit - mx);
        float ssum = e;
        #pragma unroll
        for (int m = 1; m < 8; m <<= 1)
            ssum += __shfl_xor_sync(0xffffffffu, ssum, m);
        float a = e / ssum;
        as_[r][s] = a;
        if (attn_out)
            attn_out[(size_t)(b * NPOS + n0 + r) * SLOTS + s] = a;
    }
    __syncthreads();

    // partial updates: thread owns channel c
    int c = tid;
    float acc[SLOTS];
    #pragma unroll
    for (int s = 0; s < SLOTS; s++) acc[s] = 0.f;
    #pragma unroll 8
    for (int nn = 0; nn < 32; nn++) {
        float vv = __half2float(vsm[nn][c]);
        #pragma unroll
        for (int s = 0; s < SLOTS; s++) acc[s] = fmaf(as_[nn][s], vv, acc[s]);
    }
    __half* up = g_upd + (size_t)((ch * BATCH + b) * SLOTS) * DDIM + c;
    #pragma unroll
    for (int s = 0; s < SLOTS; s++) up[(size_t)s * DDIM] = __float2half(acc[s]);
}

// ---------------- slot update: grid (64,2), 4 slots/block, 512 threads (R13) ----------------
__global__ void __launch_bounds__(512) k_slot_update(
        const float* __restrict__ bih, const float* __restrict__ bhh,
        const float* __restrict__ lg,  const float* __restrict__ lb,
        const float* __restrict__ b1,  const float* __restrict__ b2,
        const float* __restrict__ slg, const float* __restrict__ slb,
        float* __restrict__ out_slots, int write_out, int write_q) {
    int b = blockIdx.x, half = blockIdx.y;
    __shared__ float u [4][DDIM];
    __shared__ float h [4][DDIM];
    __shared__ float nh[4][DDIM];
    __shared__ float hm[4][DDIM];
    __shared__ float pr[24][DDIM];
    int tid = threadIdx.x;
    int d = tid & 255, cpart = tid >> 8;
    int c0 = cpart * 128;
    int sbase = half * 4;

    for (int i = tid; i < 4 * DDIM; i += 512) {
        int s = i >> 8, c = i & 255;
        float a = 0.f;
        #pragma unroll
        for (int chn = 0; chn < NCHUNK; chn++)
            a += __half2float(g_upd[(size_t)((chn * BATCH + b) * SLOTS + sbase + s) * DDIM + c]);
        u[s][c] = a;
        h[s][c] = g_slots[(size_t)(b * SLOTS + sbase + s) * DDIM + c];
    }
    __syncthreads();

    float ir[4] = {0,0,0,0}, iz[4] = {0,0,0,0}, in_[4] = {0,0,0,0};
    float hr[4] = {0,0,0,0}, hz[4] = {0,0,0,0}, hn_[4] = {0,0,0,0};
    #pragma unroll 4
    for (int cc = 0; cc < 128; cc++) {
        int c = c0 + cc;
        float a0 = __half2float(g_wihTh[c * 768 + d]);
        float a1 = __half2float(g_wihTh[c * 768 + 256 + d]);
        float a2 = __half2float(g_wihTh[c * 768 + 512 + d]);
        float c0w = __half2float(g_whhTh[c * 768 + d]);
        float c1w = __half2float(g_whhTh[c * 768 + 256 + d]);
        float c2w = __half2float(g_whhTh[c * 768 + 512 + d]);
        #pragma unroll
        for (int s = 0; s < 4; s++) {
            float uu = u[s][c], hh = h[s][c];
            ir[s] = fmaf(a0, uu, ir[s]); iz[s] = fmaf(a1, uu, iz[s]); in_[s] = fmaf(a2, uu, in_[s]);
            hr[s] = fmaf(c0w, hh, hr[s]); hz[s] = fmaf(c1w, hh, hz[s]); hn_[s] = fmaf(c2w, hh, hn_[s]);
        }
    }
    if (cpart == 1) {
        #pragma unroll
        for (int s = 0; s < 4; s++) {
            pr[s][d]      = ir[s];  pr[4 + s][d]  = iz[s];  pr[8 + s][d]  = in_[s];
            pr[12 + s][d] = hr[s];  pr[16 + s][d] = hz[s];  pr[20 + s][d] = hn_[s];
        }
    }
    __syncthreads();
    if (cpart == 0) {
        float bir = bih[d], biz = bih[DDIM + d], bin = bih[2 * DDIM + d];
        float bhr = bhh[d], bhz = bhh[DDIM + d], bhn = bhh[2 * DDIM + d];
        #pragma unroll
        for (int s = 0; s < 4; s++) {
            float rI = ir[s] + pr[s][d],      zI = iz[s] + pr[4 + s][d],  nI = in_[s] + pr[8 + s][d];
            float rH = hr[s] + pr[12 + s][d], zH = hz[s] + pr[16 + s][d], nH = hn_[s] + pr[20 + s][d];
            float r = 1.f / (1.f + expf(-(rI + bir + rH + bhr)));
            float z = 1.f / (1.f + expf(-(zI + biz + zH + bhz)));
            float n = tanhf(nI + bin + r * (nH + bhn));
            nh[s][d] = (1.f - z) * n + z * h[s][d];
        }
    }
    __syncthreads();

    int warp = tid >> 5, lane = tid & 31;
    if (warp < 4) {
        int s = warp;
        float v[8]; float sum = 0.f, sq = 0.f;
        #pragma unroll
        for (int j = 0; j < 8; j++) {
            v[j] = nh[s][lane + 32 * j];
            sum += v[j]; sq += v[j] * v[j];
        }
        #pragma unroll
        for (int o = 16; o; o >>= 1) {
            sum += __shfl_xor_sync(0xffffffffu, sum, o);
            sq  += __shfl_xor_sync(0xffffffffu, sq,  o);
        }
        float m = sum * (1.f / DDIM);
        float rs = rsqrtf(sq * (1.f / DDIM) - m * m + LN_EPS);
        #pragma unroll
        for (int j = 0; j < 8; j++) {
            int c = lane + 32 * j;
            u[s][c] = (v[j] - m) * rs * lg[c] + lb[c];
        }
    }
    __syncthreads();

    float m4[4] = {0,0,0,0};
    #pragma unroll 4
    for (int cc = 0; cc < 128; cc++) {
        int c = c0 + cc;
        float ww = __half2float(g_w1Th[c * DDIM + d]);
        #pragma unroll
        for (int s = 0; s < 4; s++) m4[s] = fmaf(u[s][c], ww, m4[s]);
    }
    if (cpart == 1) {
        #pragma unroll
        for (int s = 0; s < 4; s++) pr[s][d] = m4[s];
    }
    __syncthreads();
    if (cpart == 0) {
        float bb1 = b1[d];
        #pragma unroll
        for (int s = 0; s < 4; s++) hm[s][d] = fmaxf(m4[s] + pr[s][d] + bb1, 0.f);
    }
    __syncthreads();

    float o4[4] = {0,0,0,0};
    #pragma unroll 4
    for (int cc = 0; cc < 128; cc++) {
        int c = c0 + cc;
        float ww = __half2float(g_w2Th[c * DDIM + d]);
        #pragma unroll
        for (int s = 0; s < 4; s++) o4[s] = fmaf(hm[s][c], ww, o4[s]);
    }
    if (cpart == 1) {
        #pragma unroll
        for (int s = 0; s < 4; s++) pr[4 + s][d] = o4[s];
    }
    __syncthreads();
    if (cpart == 0) {
        float bb2 = b2[d];
        #pragma unroll
        for (int s = 0; s < 4; s++) {
            float res = nh[s][d] + o4[s] + pr[4 + s][d] + bb2;
            h[s][d] = res;
            g_slots[(size_t)(b * SLOTS + sbase + s) * DDIM + d] = res;
            if (write_out && out_slots)
                out_slots[(size_t)(b * SLOTS + sbase + s) * DDIM + d] = res;
        }
    }
    __syncthreads();

    if (!write_q) return;

    if (warp < 4) {
        int s = warp;
        float v[8]; float sum = 0.f, sq = 0.f;
        #pragma unroll
        for (int j = 0; j < 8; j++) {
            v[j] = h[s][lane + 32 * j];
            sum += v[j]; sq += v[j] * v[j];
        }
        #pragma unroll
        for (int o = 16; o; o >>= 1) {
            sum += __shfl_xor_sync(0xffffffffu, sum, o);
            sq  += __shfl_xor_sync(0xffffffffu, sq,  o);
        }
        float m = sum * (1.f / DDIM);
        float rs = rsqrtf(sq * (1.f / DDIM) - m * m + LN_EPS);
        #pragma unroll
        for (int j = 0; j < 8; j++) {
            int c = lane + 32 * j;
            u[s][c] = (v[j] - m) * rs * slg[c] + slb[c];
        }
    }
    __syncthreads();
    float q4[4] = {0,0,0,0};
    #pragma unroll 4
    for (int cc = 0; cc < 128; cc++) {
        int c = c0 + cc;
        float ww = __half2float(g_wqTh[c * DDIM + d]);
        #pragma unroll
        for (int s = 0; s < 4; s++) q4[s] = fmaf(u[s][c], ww, q4[s]);
    }
    if (cpart == 1) {
        #pragma unroll
        for (int s = 0; s < 4; s++) pr[8 + s][d] = q4[s];
    }
    __syncthreads();
    if (cpart == 0) {
        #pragma unroll
        for (int s = 0; s < 4; s++)
            g_q[(size_t)(b * SLOTS + sbase + s) * DDIM + d] = q4[s] + pr[8 + s][d];
    }
}

// ---------------- host launcher ----------------
extern "C" void kernel_launch(void* const* d_in, const int* in_sizes, int n_in,
                              void* d_out, int out_size) {
    const float* x        = (const float*)d_in[0];
    const float* slots_mu = (const float*)d_in[1];
    const float* ln_in_g  = (const float*)d_in[2];
    const float* ln_in_b  = (const float*)d_in[3];
    const float* wk       = (const float*)d_in[4];
    const float* wv       = (const float*)d_in[5];
    const float* ln_s_g   = (const float*)d_in[6];
    const float* ln_s_b   = (const float*)d_in[7];
    const float* wq       = (const float*)d_in[8];
    const float* gru_wih  = (const float*)d_in[9];
    const float* gru_whh  = (const float*)d_in[10];
    const float* gru_bih  = (const float*)d_in[11];
    const float* gru_bhh  = (const float*)d_in[12];
    const float* ln_m_g   = (const float*)d_in[13];
    const float* ln_m_b   = (const float*)d_in[14];
    const float* mlp_w1   = (const float*)d_in[15];
    const float* mlp_b1   = (const float*)d_in[16];
    const float* mlp_w2   = (const float*)d_in[17];
    const float* mlp_b2   = (const float*)d_in[18];

    float* out = (float*)d_out;
    float* out_slots = nullptr;
    float* out_attn  = nullptr;
    const int SLOTS_SZ = BATCH * SLOTS * DDIM;
    const int ATTN_SZ  = BATCH * NPOS * SLOTS;
    if (out_size >= SLOTS_SZ + ATTN_SZ) { out_slots = out; out_attn = out + SLOTS_SZ; }
    else if (out_size == ATTN_SZ)       { out_attn = out; }
    else                                { out_slots = out; }

    k_prep<<<2304, 256>>>(slots_mu, wk, wv, wq, gru_wih, gru_whh, mlp_w1, mlp_w2);
    k_ln_in<<<dim3(32, 64), 256>>>(x, ln_in_g, ln_in_b, ln_s_g, ln_s_b);
    k_gemm_kv_mma<<<dim3(8, 512), 256>>>();

    for (int it = 0; it < NITER; it++) {
        k_attn<<<dim3(BATCH, NCHUNK), 256>>>((it == NITER - 1) ? out_attn : nullptr,
                                             (it == 0) ? 1 : 0);
        k_slot_update<<<dim3(64, 2), 512>>>(gru_bih, gru_bhh,
                                            ln_m_g, ln_m_b, mlp_b1, mlp_b2,
                                            ln_s_g, ln_s_b,
                                            out_slots, (it == NITER - 1) ? 1 : 0,
                                            (it < NITER - 1) ? 1 : 0);
    }
}

// round 17
// speedup vs baseline: 1.0965x; 1.0165x over previous
#include <cuda_runtime.h>
#include <cuda_fp16.h>
#include <stdint.h>
#include <math.h>

#define BATCH 64
#define CDIM  256
#define NPOS  1024
#define SLOTS 8
#define DDIM  256
#define NITER 3
#define LN_EPS 1e-5f
#define ATT_SCALE 0.0625f   // D^-0.5
#define NCHUNK 32           // attention n-chunks (32 rows each)
#define KPAD  (DDIM + 8)    // fp16 smem row padding: 528B rows (16B-aligned)

// ---------------- device scratch ----------------
__device__ __half g_xh[BATCH * NPOS * CDIM];         // fp16 LN(x)
__device__ __half g_wcat[512 * CDIM];                // [n][c] fp16 (wk rows then wv rows)
__device__ __half g_kh[BATCH * NPOS * DDIM];         // fp16 k
__device__ __half g_vh[BATCH * NPOS * DDIM];         // fp16 v
__device__ float g_slots[BATCH * SLOTS * DDIM];
__device__ __half g_qh  [BATCH * SLOTS * DDIM];      // fp16 q
__device__ __half g_upd [NCHUNK * BATCH * SLOTS * DDIM];  // fp16 partials
// fp16 transposed weights [c][d]
__device__ __half g_wqTh [CDIM * DDIM];
__device__ __half g_w1Th [DDIM * DDIM];
__device__ __half g_w2Th [DDIM * DDIM];
__device__ __half g_wihTh[DDIM * 3 * DDIM];
__device__ __half g_whhTh[DDIM * 3 * DDIM];

// ---------------- helpers ----------------
__device__ __forceinline__ void cp16(void* s, const void* g) {
    unsigned sa = (unsigned)__cvta_generic_to_shared(s);
    asm volatile("cp.async.cg.shared.global [%0], [%1], 16;\n" :: "r"(sa), "l"(g));
}
__device__ __forceinline__ void cp_commit() { asm volatile("cp.async.commit_group;\n"); }
template<int N> __device__ __forceinline__ void cp_wait() {
    asm volatile("cp.async.wait_group %0;\n" :: "n"(N));
}
__device__ __forceinline__ uint4 ldm4(const void* p) {
    uint4 r;
    unsigned a = (unsigned)__cvta_generic_to_shared(p);
    asm volatile("ldmatrix.sync.aligned.m8n8.x4.shared.b16 {%0,%1,%2,%3}, [%4];"
                 : "=r"(r.x), "=r"(r.y), "=r"(r.z), "=r"(r.w) : "r"(a));
    return r;
}

// ---------------- one-time prep ----------------
__global__ void k_prep(const float* __restrict__ mu,
                       const float* __restrict__ wk, const float* __restrict__ wv,
                       const float* __restrict__ wq, const float* __restrict__ wih,
                       const float* __restrict__ whh, const float* __restrict__ w1,
                       const float* __restrict__ w2) {
    int i = blockIdx.x * 256 + threadIdx.x;
    if (i < 131072) {
        g_slots[i] = mu[i & (SLOTS * DDIM - 1)];
        float w = (i < 65536) ? wk[i] : wv[i - 65536];
        g_wcat[i] = __float2half(w);
    }
    if (i < 65536) {
        int d = i >> 8, c = i & 255;
        g_wqTh[c * 256 + d] = __float2half(wq[i]);
    } else if (i < 131072) {
        int j = i - 65536; int d = j >> 8; int c = j & 255;
        g_w1Th[c * 256 + d] = __float2half(w1[j]);
    } else if (i < 196608) {
        int j = i - 131072; int d = j >> 8; int c = j & 255;
        g_w2Th[c * 256 + d] = __float2half(w2[j]);
    } else if (i < 393216) {
        int j = i - 196608; int g = j >> 8; int c = j & 255;
        g_wihTh[c * 768 + g] = __float2half(wih[j]);
    } else if (i < 589824) {
        int j = i - 393216; int g = j >> 8; int c = j & 255;
        g_whhTh[c * 768 + g] = __float2half(whh[j]);
    }
}

// ---------------- transpose + input LayerNorm -> fp16 (+ fused iter-0 qproj) ----------------
__global__ void k_ln_in(const float* __restrict__ x,
                        const float* __restrict__ gam,
                        const float* __restrict__ bet,
                        const float* __restrict__ slg,
                        const float* __restrict__ slb) {
    __shared__ float tile[CDIM][33];
    __shared__ float mu_s[32], rs_s[32];
    int b  = blockIdx.y;
    int n0 = blockIdx.x * 32;
    int tid = threadIdx.x;
    const float* xb = x + (size_t)b * CDIM * NPOS;

    for (int i = tid; i < CDIM * 32; i += 256) {
        int c = i >> 5, n = i & 31;
        tile[c][n] = xb[c * NPOS + n0 + n];
    }
    __syncthreads();

    int warp = tid >> 5, lane = tid & 31;
    for (int col = warp; col < 32; col += 8) {
        float s = 0.f, s2 = 0.f;
        #pragma unroll
        for (int c = lane; c < CDIM; c += 32) {
            float v = tile[c][col];
            s += v; s2 += v * v;
        }
        #pragma unroll
        for (int o = 16; o; o >>= 1) {
            s  += __shfl_xor_sync(0xffffffffu, s,  o);
            s2 += __shfl_xor_sync(0xffffffffu, s2, o);
        }
        if (lane == 0) {
            float m   = s * (1.f / CDIM);
            float var = s2 * (1.f / CDIM) - m * m;
            mu_s[col] = m;
            rs_s[col] = rsqrtf(var + LN_EPS);
        }
    }
    __syncthreads();

    float gg = gam[tid], bb = bet[tid];
    size_t base = ((size_t)b * NPOS + n0) * CDIM + tid;
    #pragma unroll 8
    for (int n = 0; n < 32; n++) {
        float v = (tile[tid][n] - mu_s[n]) * rs_s[n] * gg + bb;
        g_xh[base + (size_t)n * CDIM] = __float2half(v);
    }

    // fused iter-0 q projection (4 early blocks): q = LN_s(slots_mu) @ wq^T into g_qh[batch 0]
    if (blockIdx.x != 0 || blockIdx.y >= 4) return;
    int dq = blockIdx.y;
    __syncthreads();
    float* bufa = &tile[0][0];
    float (*sn)[DDIM] = (float(*)[DDIM])bufa;
    float (*part)[SLOTS][64] = (float(*)[SLOTS][64])(bufa + 2048);

    {
        int s = warp;
        const float* row = g_slots + (size_t)s * DDIM;
        float v[8]; float sum = 0.f, sq = 0.f;
        #pragma unroll
        for (int j = 0; j < 8; j++) {
            v[j] = row[lane + 32 * j];
            sum += v[j]; sq += v[j] * v[j];
        }
        #pragma unroll
        for (int o = 16; o; o >>= 1) {
            sum += __shfl_xor_sync(0xffffffffu, sum, o);
            sq  += __shfl_xor_sync(0xffffffffu, sq,  o);
        }
        float m = sum * (1.f / DDIM);
        float r = rsqrtf(sq * (1.f / DDIM) - m * m + LN_EPS);
        #pragma unroll
        for (int j = 0; j < 8; j++) {
            int c = lane + 32 * j;
            sn[s][c] = (v[j] - m) * r * slg[c] + slb[c];
        }
    }
    __syncthreads();

    int dd = tid & 63, pp = tid >> 6;
    int d  = dq * 64 + dd;
    float acc[SLOTS];
    #pragma unroll
    for (int s = 0; s < SLOTS; s++) acc[s] = 0.f;
    #pragma unroll 8
    for (int cc = 0; cc < 64; cc++) {
        int c = pp * 64 + cc;
        float ww = __half2float(g_wqTh[c * DDIM + d]);
        #pragma unroll
        for (int s = 0; s < SLOTS; s++) acc[s] = fmaf(sn[s][c], ww, acc[s]);
    }
    #pragma unroll
    for (int s = 0; s < SLOTS; s++) part[pp][s][dd] = acc[s];
    __syncthreads();

    for (int o = tid; o < SLOTS * 64; o += 256) {
        int s = o >> 6, dd2 = o & 63;
        float v = part[0][s][dd2] + part[1][s][dd2] + part[2][s][dd2] + part[3][s][dd2];
        g_qh[(size_t)s * DDIM + dq * 64 + dd2] = __float2half(v);
    }
}

// ---------------- big GEMM: 128x64 tiles, 8 warps of 32x32, 3-stage cp.async ----------------
__global__ void __launch_bounds__(256, 4) k_gemm_kv_mma() {
    __shared__ __half As[3][128][40];
    __shared__ __half Bs[3][64][40];
    int n0 = blockIdx.x * 64;
    int m0 = blockIdx.y * 128;
    int tid = threadIdx.x, lane = tid & 31, warp = tid >> 5;
    int wm = (warp & 3) * 32, wn = (warp >> 2) * 32;
    __half* Out = (n0 < 256) ? g_kh : g_vh;
    int ncol0 = n0 & 255;

    int g8 = lane >> 3, l8 = lane & 7;
    int aro = l8 + (g8 & 1) * 8, aco = (g8 >> 1) * 8;
    int bro = l8 + (g8 >> 1) * 8, bco = (g8 & 1) * 8;

    float acc[2][4][4];
    #pragma unroll
    for (int i = 0; i < 2; i++)
        #pragma unroll
        for (int j = 0; j < 4; j++)
            #pragma unroll
            for (int q = 0; q < 4; q++) acc[i][j][q] = 0.f;

    int alr = tid >> 1, alc = (tid & 1) * 16;
    int blr = tid >> 2, blc = (tid & 3) * 8;

    auto issue = [&](int kti, int buf) {
        int kt = kti * 32;
        const __half* ga = g_xh + (size_t)(m0 + alr) * CDIM + kt + alc;
        const __half* gb = g_wcat + (size_t)(n0 + blr) * CDIM + kt + blc;
        cp16(&As[buf][alr][alc],     ga);
        cp16(&As[buf][alr][alc + 8], ga + 8);
        cp16(&Bs[buf][blr][blc],     gb);
    };

    issue(0, 0); cp_commit();
    issue(1, 1); cp_commit();

    for (int i = 0; i < 8; i++) {
        if (i < 7) cp_wait<1>(); else cp_wait<0>();
        __syncthreads();
        if (i < 6) { issue(i + 2, (i + 2) % 3); cp_commit(); }
        int buf = i % 3;

        #pragma unroll
        for (int k16 = 0; k16 < 32; k16 += 16) {
            uint4 av[2], bv[2];
            #pragma unroll
            for (int im = 0; im < 2; im++)
                av[im] = ldm4(&As[buf][wm + im * 16 + aro][k16 + aco]);
            #pragma unroll
            for (int t = 0; t < 2; t++)
                bv[t] = ldm4(&Bs[buf][wn + t * 16 + bro][k16 + bco]);

            #pragma unroll
            for (int im = 0; im < 2; im++)
                #pragma unroll
                for (int t = 0; t < 2; t++) {
                    asm volatile(
                        "mma.sync.aligned.m16n8k16.row.col.f32.f16.f16.f32 "
                        "{%0,%1,%2,%3}, {%4,%5,%6,%7}, {%8,%9}, {%0,%1,%2,%3};\n"
                        : "+f"(acc[im][2*t][0]), "+f"(acc[im][2*t][1]),
                          "+f"(acc[im][2*t][2]), "+f"(acc[im][2*t][3])
                        : "r"(av[im].x), "r"(av[im].y), "r"(av[im].z), "r"(av[im].w),
                          "r"(bv[t].x), "r"(bv[t].y));
                    asm volatile(
                        "mma.sync.aligned.m16n8k16.row.col.f32.f16.f16.f32 "
                        "{%0,%1,%2,%3}, {%4,%5,%6,%7}, {%8,%9}, {%0,%1,%2,%3};\n"
                        : "+f"(acc[im][2*t+1][0]), "+f"(acc[im][2*t+1][1]),
                          "+f"(acc[im][2*t+1][2]), "+f"(acc[im][2*t+1][3])
                        : "r"(av[im].x), "r"(av[im].y), "r"(av[im].z), "r"(av[im].w),
                          "r"(bv[t].z), "r"(bv[t].w));
                }
        }
        __syncthreads();
    }

    #pragma unroll
    for (int im = 0; im < 2; im++)
        #pragma unroll
        for (int jn = 0; jn < 4; jn++) {
            int row = m0 + wm + im * 16 + (lane >> 2);
            int col = ncol0 + wn + jn * 8 + (lane & 3) * 2;
            __half* p = Out + (size_t)row * DDIM + col;
            *(__half2*)p = __floats2half2_rn(acc[im][jn][0], acc[im][jn][1]);
            *(__half2*)(p + 8 * DDIM) = __floats2half2_rn(acc[im][jn][2], acc[im][jn][3]);
        }
}

// ---------------- attention: fp16 q, vectorized LDS everywhere ----------------
__global__ void __launch_bounds__(256) k_attn(float* __restrict__ attn_out, int q_bcast) {
    int b = blockIdx.x, ch = blockIdx.y;
    int n0 = ch * 32;
    __shared__ __half ksm[32][KPAD];
    __shared__ __half vsm[32][KPAD];
    __shared__ __half qsm[SLOTS][KPAD];
    __shared__ __align__(16) float as_[32][SLOTS];   // 32B rows, 16B-aligned
    int tid = threadIdx.x;

    {   // k,v fill via cp.async
        const __half* kg = g_kh + (size_t)(b * NPOS + n0) * DDIM;
        const __half* vg = g_vh + (size_t)(b * NPOS + n0) * DDIM;
        #pragma unroll
        for (int i = 0; i < 4; i++) {
            int idx = tid + i * 256;
            int row = idx >> 5, seg = idx & 31;
            cp16(&ksm[row][seg * 8], kg + (size_t)row * DDIM + seg * 8);
            cp16(&vsm[row][seg * 8], vg + (size_t)row * DDIM + seg * 8);
        }
        // q fill (8 rows x 32 segs = 256 cp16)
        int qb = q_bcast ? 0 : b;
        const __half* qg = g_qh + (size_t)qb * SLOTS * DDIM;
        int row = tid >> 5, seg = tid & 31;
        cp16(&qsm[row][seg * 8], qg + (size_t)row * DDIM + seg * 8);
        cp_commit();
    }
    cp_wait<0>();
    __syncthreads();

    // logits: thread-per-(row,slot), uint4 fp16 reads for both k and q
    {
        int r = tid >> 3, s = tid & 7;
        const uint4* krow = (const uint4*)&ksm[r][0];
        const uint4* qrow = (const uint4*)&qsm[s][0];
        float acc = 0.f;
        #pragma unroll 8
        for (int i = 0; i < 32; i++) {
            uint4 kq = krow[i], qq = qrow[i];
            __half2* kh = (__half2*)&kq;
            __half2* qh = (__half2*)&qq;
            #pragma unroll
            for (int j = 0; j < 4; j++) {
                float2 kf = __half22float2(kh[j]);
                float2 qf = __half22float2(qh[j]);
                acc = fmaf(kf.x, qf.x, acc);
                acc = fmaf(kf.y, qf.y, acc);
            }
        }
        float logit = acc * ATT_SCALE;
        float mx = logit;
        #pragma unroll
        for (int m = 1; m < 8; m <<= 1)
            mx = fmaxf(mx, __shfl_xor_sync(0xffffffffu, mx, m));
        float e = expf(logit - mx);
        float ssum = e;
        #pragma unroll
        for (int m = 1; m < 8; m <<= 1)
            ssum += __shfl_xor_sync(0xffffffffu, ssum, m);
        float a = e / ssum;
        as_[r][s] = a;
        if (attn_out)
            attn_out[(size_t)(b * NPOS + n0 + r) * SLOTS + s] = a;
    }
    __syncthreads();

    // partial updates: thread owns channel c; as_ via 2 broadcast LDS.128 per row
    int c = tid;
    float acc[SLOTS];
    #pragma unroll
    for (int s = 0; s < SLOTS; s++) acc[s] = 0.f;
    #pragma unroll 8
    for (int nn = 0; nn < 32; nn++) {
        float4 a0 = *(const float4*)&as_[nn][0];
        float4 a1 = *(const float4*)&as_[nn][4];
        float vv = __half2float(vsm[nn][c]);
        acc[0] = fmaf(a0.x, vv, acc[0]); acc[1] = fmaf(a0.y, vv, acc[1]);
        acc[2] = fmaf(a0.z, vv, acc[2]); acc[3] = fmaf(a0.w, vv, acc[3]);
        acc[4] = fmaf(a1.x, vv, acc[4]); acc[5] = fmaf(a1.y, vv, acc[5]);
        acc[6] = fmaf(a1.z, vv, acc[6]); acc[7] = fmaf(a1.w, vv, acc[7]);
    }
    __half* up = g_upd + (size_t)((ch * BATCH + b) * SLOTS) * DDIM + c;
    #pragma unroll
    for (int s = 0; s < SLOTS; s++) up[(size_t)s * DDIM] = __float2half(acc[s]);
}

// ---------------- slot update: grid (64,2), 4 slots/block, 512 threads ----------------
__global__ void __launch_bounds__(512) k_slot_update(
        const float* __restrict__ bih, const float* __restrict__ bhh,
        const float* __restrict__ lg,  const float* __restrict__ lb,
        const float* __restrict__ b1,  const float* __restrict__ b2,
        const float* __restrict__ slg, const float* __restrict__ slb,
        float* __restrict__ out_slots, int write_out, int write_q) {
    int b = blockIdx.x, half = blockIdx.y;
    __shared__ float u [4][DDIM];
    __shared__ float h [4][DDIM];
    __shared__ float nh[4][DDIM];
    __shared__ float hm[4][DDIM];
    __shared__ float pr[24][DDIM];
    int tid = threadIdx.x;
    int d = tid & 255, cpart = tid >> 8;
    int c0 = cpart * 128;
    int sbase = half * 4;

    for (int i = tid; i < 4 * DDIM; i += 512) {
        int s = i >> 8, c = i & 255;
        float a = 0.f;
        #pragma unroll
        for (int chn = 0; chn < NCHUNK; chn++)
            a += __half2float(g_upd[(size_t)((chn * BATCH + b) * SLOTS + sbase + s) * DDIM + c]);
        u[s][c] = a;
        h[s][c] = g_slots[(size_t)(b * SLOTS + sbase + s) * DDIM + c];
    }
    __syncthreads();

    float ir[4] = {0,0,0,0}, iz[4] = {0,0,0,0}, in_[4] = {0,0,0,0};
    float hr[4] = {0,0,0,0}, hz[4] = {0,0,0,0}, hn_[4] = {0,0,0,0};
    #pragma unroll 4
    for (int cc = 0; cc < 128; cc++) {
        int c = c0 + cc;
        float a0 = __half2float(g_wihTh[c * 768 + d]);
        float a1 = __half2float(g_wihTh[c * 768 + 256 + d]);
        float a2 = __half2float(g_wihTh[c * 768 + 512 + d]);
        float c0w = __half2float(g_whhTh[c * 768 + d]);
        float c1w = __half2float(g_whhTh[c * 768 + 256 + d]);
        float c2w = __half2float(g_whhTh[c * 768 + 512 + d]);
        #pragma unroll
        for (int s = 0; s < 4; s++) {
            float uu = u[s][c], hh = h[s][c];
            ir[s] = fmaf(a0, uu, ir[s]); iz[s] = fmaf(a1, uu, iz[s]); in_[s] = fmaf(a2, uu, in_[s]);
            hr[s] = fmaf(c0w, hh, hr[s]); hz[s] = fmaf(c1w, hh, hz[s]); hn_[s] = fmaf(c2w, hh, hn_[s]);
        }
    }
    if (cpart == 1) {
        #pragma unroll
        for (int s = 0; s < 4; s++) {
            pr[s][d]      = ir[s];  pr[4 + s][d]  = iz[s];  pr[8 + s][d]  = in_[s];
            pr[12 + s][d] = hr[s];  pr[16 + s][d] = hz[s];  pr[20 + s][d] = hn_[s];
        }
    }
    __syncthreads();
    if (cpart == 0) {
        float bir = bih[d], biz = bih[DDIM + d], bin = bih[2 * DDIM + d];
        float bhr = bhh[d], bhz = bhh[DDIM + d], bhn = bhh[2 * DDIM + d];
        #pragma unroll
        for (int s = 0; s < 4; s++) {
            float rI = ir[s] + pr[s][d],      zI = iz[s] + pr[4 + s][d],  nI = in_[s] + pr[8 + s][d];
            float rH = hr[s] + pr[12 + s][d], zH = hz[s] + pr[16 + s][d], nH = hn_[s] + pr[20 + s][d];
            float r = 1.f / (1.f + expf(-(rI + bir + rH + bhr)));
            float z = 1.f / (1.f + expf(-(zI + biz + zH + bhz)));
            float n = tanhf(nI + bin + r * (nH + bhn));
            nh[s][d] = (1.f - z) * n + z * h[s][d];
        }
    }
    __syncthreads();

    int warp = tid >> 5, lane = tid & 31;
    if (warp < 4) {
        int s = warp;
        float v[8]; float sum = 0.f, sq = 0.f;
        #pragma unroll
        for (int j = 0; j < 8; j++) {
            v[j] = nh[s][lane + 32 * j];
            sum += v[j]; sq += v[j] * v[j];
        }
        #pragma unroll
        for (int o = 16; o; o >>= 1) {
            sum += __shfl_xor_sync(0xffffffffu, sum, o);
            sq  += __shfl_xor_sync(0xffffffffu, sq,  o);
        }
        float m = sum * (1.f / DDIM);
        float rs = rsqrtf(sq * (1.f / DDIM) - m * m + LN_EPS);
        #pragma unroll
        for (int j = 0; j < 8; j++) {
            int c = lane + 32 * j;
            u[s][c] = (v[j] - m) * rs * lg[c] + lb[c];
        }
    }
    __syncthreads();

    float m4[4] = {0,0,0,0};
    #pragma unroll 4
    for (int cc = 0; cc < 128; cc++) {
        int c = c0 + cc;
        float ww = __half2float(g_w1Th[c * DDIM + d]);
        #pragma unroll
        for (int s = 0; s < 4; s++) m4[s] = fmaf(u[s][c], ww, m4[s]);
    }
    if (cpart == 1) {
        #pragma unroll
        for (int s = 0; s < 4; s++) pr[s][d] = m4[s];
    }
    __syncthreads();
    if (cpart == 0) {
        float bb1 = b1[d];
        #pragma unroll
        for (int s = 0; s < 4; s++) hm[s][d] = fmaxf(m4[s] + pr[s][d] + bb1, 0.f);
    }
    __syncthreads();

    float o4[4] = {0,0,0,0};
    #pragma unroll 4
    for (int cc = 0; cc < 128; cc++) {
        int c = c0 + cc;
        float ww = __half2float(g_w2Th[c * DDIM + d]);
        #pragma unroll
        for (int s = 0; s < 4; s++) o4[s] = fmaf(hm[s][c], ww, o4[s]);
    }
    if (cpart == 1) {
        #pragma unroll
        for (int s = 0; s < 4; s++) pr[4 + s][d] = o4[s];
    }
    __syncthreads();
    if (cpart == 0) {
        float bb2 = b2[d];
        #pragma unroll
        for (int s = 0; s < 4; s++) {
            float res = nh[s][d] + o4[s] + pr[4 + s][d] + bb2;
            h[s][d] = res;
            g_slots[(size_t)(b * SLOTS + sbase + s) * DDIM + d] = res;
            if (write_out && out_slots)
                out_slots[(size_t)(b * SLOTS + sbase + s) * DDIM + d] = res;
        }
    }
    __syncthreads();

    if (!write_q) return;

    if (warp < 4) {
        int s = warp;
        float v[8]; float sum = 0.f, sq = 0.f;
        #pragma unroll
        for (int j = 0; j < 8; j++) {
            v[j] = h[s][lane + 32 * j];
            sum += v[j]; sq += v[j] * v[j];
        }
        #pragma unroll
        for (int o = 16; o; o >>= 1) {
            sum += __shfl_xor_sync(0xffffffffu, sum, o);
            sq  += __shfl_xor_sync(0xffffffffu, sq,  o);
        }
        float m = sum * (1.f / DDIM);
        float rs = rsqrtf(sq * (1.f / DDIM) - m * m + LN_EPS);
        #pragma unroll
        for (int j = 0; j < 8; j++) {
            int c = lane + 32 * j;
            u[s][c] = (v[j] - m) * rs * slg[c] + slb[c];
        }
    }
    __syncthreads();
    float q4[4] = {0,0,0,0};
    #pragma unroll 4
    for (int cc = 0; cc < 128; cc++) {
        int c = c0 + cc;
        float ww = __half2float(g_wqTh[c * DDIM + d]);
        #pragma unroll
        for (int s = 0; s < 4; s++) q4[s] = fmaf(u[s][c], ww, q4[s]);
    }
    if (cpart == 1) {
        #pragma unroll
        for (int s = 0; s < 4; s++) pr[8 + s][d] = q4[s];
    }
    __syncthreads();
    if (cpart == 0) {
        #pragma unroll
        for (int s = 0; s < 4; s++)
            g_qh[(size_t)(b * SLOTS + sbase + s) * DDIM + d] = __float2half(q4[s] + pr[8 + s][d]);
    }
}

// ---------------- host launcher ----------------
extern "C" void kernel_launch(void* const* d_in, const int* in_sizes, int n_in,
                              void* d_out, int out_size) {
    const float* x        = (const float*)d_in[0];
    const float* slots_mu = (const float*)d_in[1];
    const float* ln_in_g  = (const float*)d_in[2];
    const float* ln_in_b  = (const float*)d_in[3];
    const float* wk       = (const float*)d_in[4];
    const float* wv       = (const float*)d_in[5];
    const float* ln_s_g   = (const float*)d_in[6];
    const float* ln_s_b   = (const float*)d_in[7];
    const float* wq       = (const float*)d_in[8];
    const float* gru_wih  = (const float*)d_in[9];
    const float* gru_whh  = (const float*)d_in[10];
    const float* gru_bih  = (const float*)d_in[11];
    const float* gru_bhh  = (const float*)d_in[12];
    const float* ln_m_g   = (const float*)d_in[13];
    const float* ln_m_b   = (const float*)d_in[14];
    const float* mlp_w1   = (const float*)d_in[15];
    const float* mlp_b1   = (const float*)d_in[16];
    const float* mlp_w2   = (const float*)d_in[17];
    const float* mlp_b2   = (const float*)d_in[18];

    float* out = (float*)d_out;
    float* out_slots = nullptr;
    float* out_attn  = nullptr;
    const int SLOTS_SZ = BATCH * SLOTS * DDIM;
    const int ATTN_SZ  = BATCH * NPOS * SLOTS;
    if (out_size >= SLOTS_SZ + ATTN_SZ) { out_slots = out; out_attn = out + SLOTS_SZ; }
    else if (out_size == ATTN_SZ)       { out_attn = out; }
    else                                { out_slots = out; }

    k_prep<<<2304, 256>>>(slots_mu, wk, wv, wq, gru_wih, gru_whh, mlp_w1, mlp_w2);
    k_ln_in<<<dim3(32, 64), 256>>>(x, ln_in_g, ln_in_b, ln_s_g, ln_s_b);
    k_gemm_kv_mma<<<dim3(8, 512), 256>>>();

    for (int it = 0; it < NITER; it++) {
        k_attn<<<dim3(BATCH, NCHUNK), 256>>>((it == NITER - 1) ? out_attn : nullptr,
                                             (it == 0) ? 1 : 0);
        k_slot_update<<<dim3(64, 2), 512>>>(gru_bih, gru_bhh,
                                            ln_m_g, ln_m_b, mlp_b1, mlp_b2,
                                            ln_s_g, ln_s_b,
                                            out_slots, (it == NITER - 1) ? 1 : 0,
                                            (it < NITER - 1) ? 1 : 0);
    }
}